// round 1
// baseline (speedup 1.0000x reference)
#include <cuda_runtime.h>
#include <math.h>
#include <stdint.h>

// Problem constants (fixed by the reference)
#define DM    1024
#define HH    16
#define DKH   64
#define BATCH 4
#define SEQ   2048
#define MTOT  (BATCH * SEQ)   // 8192

// ---------------------------------------------------------------------------
// Scratch (no allocations allowed -> __device__ globals)
// ---------------------------------------------------------------------------
__device__ __align__(128) float g_Q[(size_t)MTOT * DM];
__device__ __align__(128) float g_K[(size_t)MTOT * DM];
__device__ __align__(128) float g_V[(size_t)MTOT * DM];
__device__ __align__(128) float g_ctx[(size_t)MTOT * DM];

// ---------------------------------------------------------------------------
// GEMM NT: C[M, N] = A[M, K] * B[N, K]^T   (y = x @ W.T)
// M = 8192, N = K = 1024 (hardcoded tile-exact).
// 128x128 block tile, BK=8, 256 threads, 8x8 per-thread micro tile.
// ---------------------------------------------------------------------------
__global__ __launch_bounds__(256)
void gemm_nt_kernel(const float* __restrict__ A,
                    const float* __restrict__ B,
                    float* __restrict__ C)
{
    const int K = DM;
    const int N = DM;

    __shared__ float As[8][128];
    __shared__ float Bs[8][128];

    const int bm = blockIdx.y * 128;
    const int bn = blockIdx.x * 128;
    const int tid = threadIdx.x;

    const int lrow = tid >> 1;          // 0..127 (row within tile for loads)
    const int lk   = (tid & 1) * 4;     // 0 or 4

    const int ty = tid >> 4;            // 0..15
    const int tx = tid & 15;            // 0..15

    const float* Aptr = A + (size_t)(bm + lrow) * K + lk;
    const float* Bptr = B + (size_t)(bn + lrow) * K + lk;

    float acc[8][8];
#pragma unroll
    for (int i = 0; i < 8; i++)
#pragma unroll
        for (int j = 0; j < 8; j++) acc[i][j] = 0.f;

    for (int k0 = 0; k0 < K; k0 += 8) {
        float4 a = *(const float4*)(Aptr + k0);
        float4 b = *(const float4*)(Bptr + k0);
        As[lk + 0][lrow] = a.x;
        As[lk + 1][lrow] = a.y;
        As[lk + 2][lrow] = a.z;
        As[lk + 3][lrow] = a.w;
        Bs[lk + 0][lrow] = b.x;
        Bs[lk + 1][lrow] = b.y;
        Bs[lk + 2][lrow] = b.z;
        Bs[lk + 3][lrow] = b.w;
        __syncthreads();

#pragma unroll
        for (int kk = 0; kk < 8; kk++) {
            float4 ra0 = *(const float4*)&As[kk][ty * 8];
            float4 ra1 = *(const float4*)&As[kk][ty * 8 + 4];
            float4 rb0 = *(const float4*)&Bs[kk][tx * 8];
            float4 rb1 = *(const float4*)&Bs[kk][tx * 8 + 4];
            float ra[8] = {ra0.x, ra0.y, ra0.z, ra0.w, ra1.x, ra1.y, ra1.z, ra1.w};
            float rb[8] = {rb0.x, rb0.y, rb0.z, rb0.w, rb1.x, rb1.y, rb1.z, rb1.w};
#pragma unroll
            for (int i = 0; i < 8; i++)
#pragma unroll
                for (int j = 0; j < 8; j++)
                    acc[i][j] = fmaf(ra[i], rb[j], acc[i][j]);
        }
        __syncthreads();
    }

    // Epilogue: tile-exact, no bounds checks needed.
#pragma unroll
    for (int i = 0; i < 8; i++) {
        float* crow = C + (size_t)(bm + ty * 8 + i) * N + bn + tx * 8;
        float4 c0 = make_float4(acc[i][0], acc[i][1], acc[i][2], acc[i][3]);
        float4 c1 = make_float4(acc[i][4], acc[i][5], acc[i][6], acc[i][7]);
        *(float4*)(crow)     = c0;
        *(float4*)(crow + 4) = c1;
    }
}

// ---------------------------------------------------------------------------
// Flash attention (fp32): one block per (b*H + h, q-tile of 64 rows).
// Q,K,V are the projected tensors in [B, S, DM] layout; head h uses columns
// [h*64, h*64+64). ctx written in the same layout.
// 256 threads: 16x16 thread grid, 4x4 micro tiles over 64x64 score / O tiles.
// ---------------------------------------------------------------------------
#define LD 68   // smem row pitch (pad), multiple of 4 for float4 alignment

__global__ __launch_bounds__(256)
void attn_kernel(const float* __restrict__ Q,
                 const float* __restrict__ K,
                 const float* __restrict__ V,
                 float* __restrict__ ctx)
{
    const int bh = blockIdx.x;           // 0..63
    const int b  = bh / HH;
    const int h  = bh % HH;
    const int q0 = blockIdx.y * 64;

    extern __shared__ float sm[];
    float* Qs = sm;                 // [64][LD]  transposed: Qs[d][q]
    float* Ks = Qs + 64 * LD;       // [64][LD]  transposed: Ks[d][k]
    float* Vs = Ks + 64 * LD;       // [64][LD]  natural:    Vs[k][d]
    float* Ss = Vs + 64 * LD;       // [64][LD]  scores:     Ss[q][k]
    float* m_s = Ss + 64 * LD;      // [64]
    float* l_s = m_s + 64;          // [64]
    float* a_s = l_s + 64;          // [64] alpha

    const int tid = threadIdx.x;
    const int ty  = tid >> 4;       // 0..15 -> q rows ty*4..+3
    const int tx  = tid & 15;       // 0..15 -> cols tx*4..+3
    const float scale = 0.125f;     // 1/sqrt(64)

    const int dld = tid & 63;       // load lane: feature index
    const int rld = tid >> 6;       // load lane: row phase 0..3

    const float* Qbase = Q + ((size_t)b * SEQ + q0) * DM + h * DKH;
    const float* Kbase = K + (size_t)b * SEQ * DM + h * DKH;
    const float* Vbase = V + (size_t)b * SEQ * DM + h * DKH;

    // Load Q tile transposed (and pre-scaled)
#pragma unroll
    for (int r = rld; r < 64; r += 4)
        Qs[dld * LD + r] = Qbase[(size_t)r * DM + dld] * scale;

    if (tid < 64) { m_s[tid] = -INFINITY; l_s[tid] = 0.f; }

    float Oacc[4][4];
#pragma unroll
    for (int i = 0; i < 4; i++)
#pragma unroll
        for (int j = 0; j < 4; j++) Oacc[i][j] = 0.f;

    __syncthreads();

    for (int kt = 0; kt < SEQ; kt += 64) {
        // Load K (transposed) and V (natural)
#pragma unroll
        for (int r = rld; r < 64; r += 4) {
            Ks[dld * LD + r]  = Kbase[(size_t)(kt + r) * DM + dld];
            Vs[r * LD + dld]  = Vbase[(size_t)(kt + r) * DM + dld];
        }
        __syncthreads();

        // S = Q @ K^T  (64x64), thread computes 4x4
        float sacc[4][4];
#pragma unroll
        for (int i = 0; i < 4; i++)
#pragma unroll
            for (int j = 0; j < 4; j++) sacc[i][j] = 0.f;

#pragma unroll 8
        for (int d = 0; d < 64; d++) {
            float4 rq = *(const float4*)&Qs[d * LD + ty * 4];
            float4 rk = *(const float4*)&Ks[d * LD + tx * 4];
            float q[4] = {rq.x, rq.y, rq.z, rq.w};
            float kx[4] = {rk.x, rk.y, rk.z, rk.w};
#pragma unroll
            for (int i = 0; i < 4; i++)
#pragma unroll
                for (int j = 0; j < 4; j++)
                    sacc[i][j] = fmaf(q[i], kx[j], sacc[i][j]);
        }
#pragma unroll
        for (int i = 0; i < 4; i++)
            *(float4*)&Ss[(ty * 4 + i) * LD + tx * 4] =
                make_float4(sacc[i][0], sacc[i][1], sacc[i][2], sacc[i][3]);
        __syncthreads();

        // Online softmax: 4 threads per row, 16 elems each
        {
            const int row = tid >> 2;
            const int seg = (tid & 3) * 16;
            float* srow = &Ss[row * LD + seg];

            float mx = -INFINITY;
#pragma unroll
            for (int i = 0; i < 16; i++) mx = fmaxf(mx, srow[i]);
            mx = fmaxf(mx, __shfl_xor_sync(0xffffffffu, mx, 1));
            mx = fmaxf(mx, __shfl_xor_sync(0xffffffffu, mx, 2));

            const float mold = m_s[row];
            const float mnew = fmaxf(mold, mx);

            float sum = 0.f;
#pragma unroll
            for (int i = 0; i < 16; i++) {
                float p = __expf(srow[i] - mnew);
                srow[i] = p;
                sum += p;
            }
            sum += __shfl_xor_sync(0xffffffffu, sum, 1);
            sum += __shfl_xor_sync(0xffffffffu, sum, 2);

            const float alpha = __expf(mold - mnew);
            if ((tid & 3) == 0) {
                m_s[row] = mnew;
                l_s[row] = l_s[row] * alpha + sum;
                a_s[row] = alpha;
            }
        }
        __syncthreads();

        // O = O*alpha + P @ V
#pragma unroll
        for (int i = 0; i < 4; i++) {
            const float a = a_s[ty * 4 + i];
#pragma unroll
            for (int j = 0; j < 4; j++) Oacc[i][j] *= a;
        }
#pragma unroll 8
        for (int k = 0; k < 64; k++) {
            float4 rv = *(const float4*)&Vs[k * LD + tx * 4];
            float v[4] = {rv.x, rv.y, rv.z, rv.w};
            float p[4];
#pragma unroll
            for (int i = 0; i < 4; i++) p[i] = Ss[(ty * 4 + i) * LD + k];
#pragma unroll
            for (int i = 0; i < 4; i++)
#pragma unroll
                for (int j = 0; j < 4; j++)
                    Oacc[i][j] = fmaf(p[i], v[j], Oacc[i][j]);
        }
        __syncthreads();
    }

    // Epilogue: normalize and store ctx in [B, S, DM] layout
    float* out = ctx + ((size_t)b * SEQ + q0) * DM + h * DKH;
#pragma unroll
    for (int i = 0; i < 4; i++) {
        const float inv = 1.f / l_s[ty * 4 + i];
        float4 o = make_float4(Oacc[i][0] * inv, Oacc[i][1] * inv,
                               Oacc[i][2] * inv, Oacc[i][3] * inv);
        *(float4*)(out + (size_t)(ty * 4 + i) * DM + tx * 4) = o;
    }
}

// ---------------------------------------------------------------------------
// Launch
// ---------------------------------------------------------------------------
extern "C" void kernel_launch(void* const* d_in, const int* in_sizes, int n_in,
                              void* d_out, int out_size)
{
    (void)in_sizes; (void)n_in; (void)out_size;
    const float* q  = (const float*)d_in[0];
    const float* k  = (const float*)d_in[1];
    const float* v  = (const float*)d_in[2];
    const float* Wq = (const float*)d_in[3];
    const float* Wk = (const float*)d_in[4];
    const float* Wv = (const float*)d_in[5];
    const float* Wo = (const float*)d_in[6];
    float* out = (float*)d_out;

    float *gQ, *gK, *gV, *gC;
    cudaGetSymbolAddress((void**)&gQ, g_Q);
    cudaGetSymbolAddress((void**)&gK, g_K);
    cudaGetSymbolAddress((void**)&gV, g_V);
    cudaGetSymbolAddress((void**)&gC, g_ctx);

    const int attn_smem = (4 * 64 * LD + 3 * 64) * (int)sizeof(float);
    static bool attr_set = false;
    if (!attr_set) {
        cudaFuncSetAttribute(attn_kernel,
                             cudaFuncAttributeMaxDynamicSharedMemorySize,
                             attn_smem);
        attr_set = true;
    }

    dim3 ggrid(DM / 128, MTOT / 128);   // (8, 64)
    gemm_nt_kernel<<<ggrid, 256>>>(q, Wq, gQ);
    gemm_nt_kernel<<<ggrid, 256>>>(k, Wk, gK);
    gemm_nt_kernel<<<ggrid, 256>>>(v, Wv, gV);

    dim3 agrid(BATCH * HH, SEQ / 64);   // (64, 32)
    attn_kernel<<<agrid, 256, attn_smem>>>(gQ, gK, gV, gC);

    gemm_nt_kernel<<<ggrid, 256>>>(gC, Wo, out);
}

// round 2
// speedup vs baseline: 1.5320x; 1.5320x over previous
#include <cuda_runtime.h>
#include <math.h>
#include <stdint.h>

// Problem constants (fixed by the reference)
#define DM    1024
#define HH    16
#define DKH   64
#define BATCH 4
#define SEQ   2048
#define MTOT  (BATCH * SEQ)   // 8192

// ---------------------------------------------------------------------------
// Scratch (no allocations allowed -> __device__ globals)
// ---------------------------------------------------------------------------
__device__ __align__(128) float g_Q[(size_t)MTOT * DM];
__device__ __align__(128) float g_K[(size_t)MTOT * DM];
__device__ __align__(128) float g_V[(size_t)MTOT * DM];
__device__ __align__(128) float g_ctx[(size_t)MTOT * DM];

// ---------------------------------------------------------------------------
// TF32 helpers
// ---------------------------------------------------------------------------
__device__ __forceinline__ float f2tf32(float x) {
    uint32_t r;
    asm("cvt.rna.tf32.f32 %0, %1;" : "=r"(r) : "f"(x));
    return __uint_as_float(r);
}

__device__ __forceinline__ void mma_tf32(float (&d)[4],
                                         const uint32_t (&a)[4],
                                         const uint32_t (&b)[2]) {
    asm volatile(
        "mma.sync.aligned.m16n8k8.row.col.f32.tf32.tf32.f32 "
        "{%0,%1,%2,%3}, {%4,%5,%6,%7}, {%8,%9}, {%0,%1,%2,%3};"
        : "+f"(d[0]), "+f"(d[1]), "+f"(d[2]), "+f"(d[3])
        : "r"(a[0]), "r"(a[1]), "r"(a[2]), "r"(a[3]),
          "r"(b[0]), "r"(b[1]));
}

// ---------------------------------------------------------------------------
// TF32 tensor-core GEMM NT: C[M,N] = A[M,K] * B[N,K]^T  (y = x @ W.T)
// M = 8192 (rows multiple of 128), N = K = 1024. 128x128x16 block tile,
// 256 threads = 8 warps in 2(m) x 4(n); warp tile 64x32 via m16n8k8 frags.
// Double-buffered smem, register prefetch. Smem pitch 20 floats ->
// conflict-free fragment loads (bank = (20g + tg + ks) % 32 covers 0..31).
// ---------------------------------------------------------------------------
#define GP 20   // smem row pitch in floats (16 + 4 pad)

__global__ __launch_bounds__(256)
void gemm_tf32_kernel(const float* __restrict__ A,
                      const float* __restrict__ B,
                      float* __restrict__ C)
{
    __shared__ float As[2][128 * GP];
    __shared__ float Bs[2][128 * GP];

    const int tid = threadIdx.x;
    const int bm = blockIdx.y * 128;
    const int bn = blockIdx.x * 128;

    const int lane = tid & 31;
    const int wid  = tid >> 5;
    const int wm   = wid >> 2;          // 0..1  -> 64 rows
    const int wn   = wid & 3;           // 0..3  -> 32 cols
    const int g    = lane >> 2;         // 0..7
    const int tg   = lane & 3;          // 0..3

    // loader mapping: idx in [0,512): m = idx>>2 (0..127), kq = idx&3
    const int m0  = tid >> 2;           // iter 0 row
    const int kq4 = (tid & 3) * 4;      // k sub-offset (floats)

    float4 pa[2], pb[2];

    float acc[4][4][4];
#pragma unroll
    for (int i = 0; i < 4; i++)
#pragma unroll
        for (int j = 0; j < 4; j++)
#pragma unroll
            for (int c = 0; c < 4; c++) acc[i][j][c] = 0.f;

    // ---- fetch tile (k0) into registers ----
    auto fetch = [&](int k0) {
#pragma unroll
        for (int i = 0; i < 2; i++) {
            int m = m0 + i * 64;
            pa[i] = *(const float4*)(A + (size_t)(bm + m) * DM + k0 + kq4);
            pb[i] = *(const float4*)(B + (size_t)(bn + m) * DM + k0 + kq4);
        }
    };
    // ---- stash registers into smem buffer (with tf32 rounding) ----
    auto stash = [&](int buf) {
#pragma unroll
        for (int i = 0; i < 2; i++) {
            int m = m0 + i * 64;
            float* a = &As[buf][m * GP + kq4];
            float* b = &Bs[buf][m * GP + kq4];
            a[0] = f2tf32(pa[i].x); a[1] = f2tf32(pa[i].y);
            a[2] = f2tf32(pa[i].z); a[3] = f2tf32(pa[i].w);
            b[0] = f2tf32(pb[i].x); b[1] = f2tf32(pb[i].y);
            b[2] = f2tf32(pb[i].z); b[3] = f2tf32(pb[i].w);
        }
    };

    fetch(0);
    stash(0);
    __syncthreads();

    int buf = 0;
    for (int k0 = 0; k0 < DM; k0 += 16) {
        const bool more = (k0 + 16 < DM);
        if (more) fetch(k0 + 16);

        const float* as = As[buf];
        const float* bs = Bs[buf];
#pragma unroll
        for (int ks = 0; ks < 16; ks += 8) {
            uint32_t af[4][4];
            uint32_t bf[4][2];
#pragma unroll
            for (int mf = 0; mf < 4; mf++) {
                const float* p = &as[(wm * 64 + mf * 16 + g) * GP + ks + tg];
                af[mf][0] = __float_as_uint(p[0]);
                af[mf][1] = __float_as_uint(p[8 * GP]);
                af[mf][2] = __float_as_uint(p[4]);
                af[mf][3] = __float_as_uint(p[8 * GP + 4]);
            }
#pragma unroll
            for (int nf = 0; nf < 4; nf++) {
                const float* p = &bs[(wn * 32 + nf * 8 + g) * GP + ks + tg];
                bf[nf][0] = __float_as_uint(p[0]);
                bf[nf][1] = __float_as_uint(p[4]);
            }
#pragma unroll
            for (int mf = 0; mf < 4; mf++)
#pragma unroll
                for (int nf = 0; nf < 4; nf++)
                    mma_tf32(acc[mf][nf], af[mf], bf[nf]);
        }

        if (more) {
            stash(buf ^ 1);
            __syncthreads();
            buf ^= 1;
        }
    }

    // Epilogue: c0,c1 at (row g, col 2tg), c2,c3 at (row g+8, col 2tg)
#pragma unroll
    for (int mf = 0; mf < 4; mf++) {
#pragma unroll
        for (int nf = 0; nf < 4; nf++) {
            float* cp = C + (size_t)(bm + wm * 64 + mf * 16 + g) * DM
                          + bn + wn * 32 + nf * 8 + tg * 2;
            *(float2*)cp = make_float2(acc[mf][nf][0], acc[mf][nf][1]);
            *(float2*)(cp + 8 * DM) = make_float2(acc[mf][nf][2], acc[mf][nf][3]);
        }
    }
}

// ---------------------------------------------------------------------------
// Flash attention (fp32): unchanged from round 1 (proven correct).
// ---------------------------------------------------------------------------
#define LD 68   // smem row pitch (pad), multiple of 4 for float4 alignment

__global__ __launch_bounds__(256)
void attn_kernel(const float* __restrict__ Q,
                 const float* __restrict__ K,
                 const float* __restrict__ V,
                 float* __restrict__ ctx)
{
    const int bh = blockIdx.x;           // 0..63
    const int b  = bh / HH;
    const int h  = bh % HH;
    const int q0 = blockIdx.y * 64;

    extern __shared__ float sm[];
    float* Qs = sm;                 // [64][LD]  transposed: Qs[d][q]
    float* Ks = Qs + 64 * LD;       // [64][LD]  transposed: Ks[d][k]
    float* Vs = Ks + 64 * LD;       // [64][LD]  natural:    Vs[k][d]
    float* Ss = Vs + 64 * LD;       // [64][LD]  scores:     Ss[q][k]
    float* m_s = Ss + 64 * LD;      // [64]
    float* l_s = m_s + 64;          // [64]
    float* a_s = l_s + 64;          // [64] alpha

    const int tid = threadIdx.x;
    const int ty  = tid >> 4;       // 0..15 -> q rows ty*4..+3
    const int tx  = tid & 15;       // 0..15 -> cols tx*4..+3
    const float scale = 0.125f;     // 1/sqrt(64)

    const int dld = tid & 63;       // load lane: feature index
    const int rld = tid >> 6;       // load lane: row phase 0..3

    const float* Qbase = Q + ((size_t)b * SEQ + q0) * DM + h * DKH;
    const float* Kbase = K + (size_t)b * SEQ * DM + h * DKH;
    const float* Vbase = V + (size_t)b * SEQ * DM + h * DKH;

    // Load Q tile transposed (and pre-scaled)
#pragma unroll
    for (int r = rld; r < 64; r += 4)
        Qs[dld * LD + r] = Qbase[(size_t)r * DM + dld] * scale;

    if (tid < 64) { m_s[tid] = -INFINITY; l_s[tid] = 0.f; }

    float Oacc[4][4];
#pragma unroll
    for (int i = 0; i < 4; i++)
#pragma unroll
        for (int j = 0; j < 4; j++) Oacc[i][j] = 0.f;

    __syncthreads();

    for (int kt = 0; kt < SEQ; kt += 64) {
        // Load K (transposed) and V (natural)
#pragma unroll
        for (int r = rld; r < 64; r += 4) {
            Ks[dld * LD + r]  = Kbase[(size_t)(kt + r) * DM + dld];
            Vs[r * LD + dld]  = Vbase[(size_t)(kt + r) * DM + dld];
        }
        __syncthreads();

        // S = Q @ K^T  (64x64), thread computes 4x4
        float sacc[4][4];
#pragma unroll
        for (int i = 0; i < 4; i++)
#pragma unroll
            for (int j = 0; j < 4; j++) sacc[i][j] = 0.f;

#pragma unroll 8
        for (int d = 0; d < 64; d++) {
            float4 rq = *(const float4*)&Qs[d * LD + ty * 4];
            float4 rk = *(const float4*)&Ks[d * LD + tx * 4];
            float q[4] = {rq.x, rq.y, rq.z, rq.w};
            float kx[4] = {rk.x, rk.y, rk.z, rk.w};
#pragma unroll
            for (int i = 0; i < 4; i++)
#pragma unroll
                for (int j = 0; j < 4; j++)
                    sacc[i][j] = fmaf(q[i], kx[j], sacc[i][j]);
        }
#pragma unroll
        for (int i = 0; i < 4; i++)
            *(float4*)&Ss[(ty * 4 + i) * LD + tx * 4] =
                make_float4(sacc[i][0], sacc[i][1], sacc[i][2], sacc[i][3]);
        __syncthreads();

        // Online softmax: 4 threads per row, 16 elems each
        {
            const int row = tid >> 2;
            const int seg = (tid & 3) * 16;
            float* srow = &Ss[row * LD + seg];

            float mx = -INFINITY;
#pragma unroll
            for (int i = 0; i < 16; i++) mx = fmaxf(mx, srow[i]);
            mx = fmaxf(mx, __shfl_xor_sync(0xffffffffu, mx, 1));
            mx = fmaxf(mx, __shfl_xor_sync(0xffffffffu, mx, 2));

            const float mold = m_s[row];
            const float mnew = fmaxf(mold, mx);

            float sum = 0.f;
#pragma unroll
            for (int i = 0; i < 16; i++) {
                float p = __expf(srow[i] - mnew);
                srow[i] = p;
                sum += p;
            }
            sum += __shfl_xor_sync(0xffffffffu, sum, 1);
            sum += __shfl_xor_sync(0xffffffffu, sum, 2);

            const float alpha = __expf(mold - mnew);
            if ((tid & 3) == 0) {
                m_s[row] = mnew;
                l_s[row] = l_s[row] * alpha + sum;
                a_s[row] = alpha;
            }
        }
        __syncthreads();

        // O = O*alpha + P @ V
#pragma unroll
        for (int i = 0; i < 4; i++) {
            const float a = a_s[ty * 4 + i];
#pragma unroll
            for (int j = 0; j < 4; j++) Oacc[i][j] *= a;
        }
#pragma unroll 8
        for (int k = 0; k < 64; k++) {
            float4 rv = *(const float4*)&Vs[k * LD + tx * 4];
            float v[4] = {rv.x, rv.y, rv.z, rv.w};
            float p[4];
#pragma unroll
            for (int i = 0; i < 4; i++) p[i] = Ss[(ty * 4 + i) * LD + k];
#pragma unroll
            for (int i = 0; i < 4; i++)
#pragma unroll
                for (int j = 0; j < 4; j++)
                    Oacc[i][j] = fmaf(p[i], v[j], Oacc[i][j]);
        }
        __syncthreads();
    }

    // Epilogue: normalize and store ctx in [B, S, DM] layout
    float* out = ctx + ((size_t)b * SEQ + q0) * DM + h * DKH;
#pragma unroll
    for (int i = 0; i < 4; i++) {
        const float inv = 1.f / l_s[ty * 4 + i];
        float4 o = make_float4(Oacc[i][0] * inv, Oacc[i][1] * inv,
                               Oacc[i][2] * inv, Oacc[i][3] * inv);
        *(float4*)(out + (size_t)(ty * 4 + i) * DM + tx * 4) = o;
    }
}

// ---------------------------------------------------------------------------
// Launch
// ---------------------------------------------------------------------------
extern "C" void kernel_launch(void* const* d_in, const int* in_sizes, int n_in,
                              void* d_out, int out_size)
{
    (void)in_sizes; (void)n_in; (void)out_size;
    const float* q  = (const float*)d_in[0];
    const float* k  = (const float*)d_in[1];
    const float* v  = (const float*)d_in[2];
    const float* Wq = (const float*)d_in[3];
    const float* Wk = (const float*)d_in[4];
    const float* Wv = (const float*)d_in[5];
    const float* Wo = (const float*)d_in[6];
    float* out = (float*)d_out;

    float *gQ, *gK, *gV, *gC;
    cudaGetSymbolAddress((void**)&gQ, g_Q);
    cudaGetSymbolAddress((void**)&gK, g_K);
    cudaGetSymbolAddress((void**)&gV, g_V);
    cudaGetSymbolAddress((void**)&gC, g_ctx);

    const int attn_smem = (4 * 64 * LD + 3 * 64) * (int)sizeof(float);
    static bool attr_set = false;
    if (!attr_set) {
        cudaFuncSetAttribute(attn_kernel,
                             cudaFuncAttributeMaxDynamicSharedMemorySize,
                             attn_smem);
        attr_set = true;
    }

    dim3 ggrid(DM / 128, MTOT / 128);   // (8, 64)
    gemm_tf32_kernel<<<ggrid, 256>>>(q, Wq, gQ);
    gemm_tf32_kernel<<<ggrid, 256>>>(k, Wk, gK);
    gemm_tf32_kernel<<<ggrid, 256>>>(v, Wv, gV);

    dim3 agrid(BATCH * HH, SEQ / 64);   // (64, 32)
    attn_kernel<<<agrid, 256, attn_smem>>>(gQ, gK, gV, gC);

    gemm_tf32_kernel<<<ggrid, 256>>>(gC, Wo, out);
}

// round 3
// speedup vs baseline: 2.8853x; 1.8834x over previous
#include <cuda_runtime.h>
#include <math.h>
#include <stdint.h>

// Problem constants (fixed by the reference)
#define DM    1024
#define HH    16
#define DKH   64
#define BATCH 4
#define SEQ   2048
#define MTOT  (BATCH * SEQ)   // 8192

// ---------------------------------------------------------------------------
// Scratch (no allocations allowed -> __device__ globals)
// ---------------------------------------------------------------------------
__device__ __align__(128) float g_Q[(size_t)MTOT * DM];
__device__ __align__(128) float g_K[(size_t)MTOT * DM];
__device__ __align__(128) float g_V[(size_t)MTOT * DM];
__device__ __align__(128) float g_ctx[(size_t)MTOT * DM];

// ---------------------------------------------------------------------------
// TF32 helpers
// ---------------------------------------------------------------------------
__device__ __forceinline__ float f2tf32(float x) {
    uint32_t r;
    asm("cvt.rna.tf32.f32 %0, %1;" : "=r"(r) : "f"(x));
    return __uint_as_float(r);
}

__device__ __forceinline__ void mma_tf32(float (&d)[4],
                                         const uint32_t (&a)[4],
                                         const uint32_t (&b)[2]) {
    asm volatile(
        "mma.sync.aligned.m16n8k8.row.col.f32.tf32.tf32.f32 "
        "{%0,%1,%2,%3}, {%4,%5,%6,%7}, {%8,%9}, {%0,%1,%2,%3};"
        : "+f"(d[0]), "+f"(d[1]), "+f"(d[2]), "+f"(d[3])
        : "r"(a[0]), "r"(a[1]), "r"(a[2]), "r"(a[3]),
          "r"(b[0]), "r"(b[1]));
}

// ---------------------------------------------------------------------------
// TF32 tensor-core GEMM NT: C[M,N] = A[M,K] * B[N,K]^T  (y = x @ W.T)
// (unchanged from round 2 — verified correct)
// ---------------------------------------------------------------------------
#define GP 20   // smem row pitch in floats (16 + 4 pad)

__global__ __launch_bounds__(256)
void gemm_tf32_kernel(const float* __restrict__ A,
                      const float* __restrict__ B,
                      float* __restrict__ C)
{
    __shared__ float As[2][128 * GP];
    __shared__ float Bs[2][128 * GP];

    const int tid = threadIdx.x;
    const int bm = blockIdx.y * 128;
    const int bn = blockIdx.x * 128;

    const int lane = tid & 31;
    const int wid  = tid >> 5;
    const int wm   = wid >> 2;
    const int wn   = wid & 3;
    const int g    = lane >> 2;
    const int tg   = lane & 3;

    const int m0  = tid >> 2;
    const int kq4 = (tid & 3) * 4;

    float4 pa[2], pb[2];

    float acc[4][4][4];
#pragma unroll
    for (int i = 0; i < 4; i++)
#pragma unroll
        for (int j = 0; j < 4; j++)
#pragma unroll
            for (int c = 0; c < 4; c++) acc[i][j][c] = 0.f;

    auto fetch = [&](int k0) {
#pragma unroll
        for (int i = 0; i < 2; i++) {
            int m = m0 + i * 64;
            pa[i] = *(const float4*)(A + (size_t)(bm + m) * DM + k0 + kq4);
            pb[i] = *(const float4*)(B + (size_t)(bn + m) * DM + k0 + kq4);
        }
    };
    auto stash = [&](int buf) {
#pragma unroll
        for (int i = 0; i < 2; i++) {
            int m = m0 + i * 64;
            float* a = &As[buf][m * GP + kq4];
            float* b = &Bs[buf][m * GP + kq4];
            a[0] = f2tf32(pa[i].x); a[1] = f2tf32(pa[i].y);
            a[2] = f2tf32(pa[i].z); a[3] = f2tf32(pa[i].w);
            b[0] = f2tf32(pb[i].x); b[1] = f2tf32(pb[i].y);
            b[2] = f2tf32(pb[i].z); b[3] = f2tf32(pb[i].w);
        }
    };

    fetch(0);
    stash(0);
    __syncthreads();

    int buf = 0;
    for (int k0 = 0; k0 < DM; k0 += 16) {
        const bool more = (k0 + 16 < DM);
        if (more) fetch(k0 + 16);

        const float* as = As[buf];
        const float* bs = Bs[buf];
#pragma unroll
        for (int ks = 0; ks < 16; ks += 8) {
            uint32_t af[4][4];
            uint32_t bf[4][2];
#pragma unroll
            for (int mf = 0; mf < 4; mf++) {
                const float* p = &as[(wm * 64 + mf * 16 + g) * GP + ks + tg];
                af[mf][0] = __float_as_uint(p[0]);
                af[mf][1] = __float_as_uint(p[8 * GP]);
                af[mf][2] = __float_as_uint(p[4]);
                af[mf][3] = __float_as_uint(p[8 * GP + 4]);
            }
#pragma unroll
            for (int nf = 0; nf < 4; nf++) {
                const float* p = &bs[(wn * 32 + nf * 8 + g) * GP + ks + tg];
                bf[nf][0] = __float_as_uint(p[0]);
                bf[nf][1] = __float_as_uint(p[4]);
            }
#pragma unroll
            for (int mf = 0; mf < 4; mf++)
#pragma unroll
                for (int nf = 0; nf < 4; nf++)
                    mma_tf32(acc[mf][nf], af[mf], bf[nf]);
        }

        if (more) {
            stash(buf ^ 1);
            __syncthreads();
            buf ^= 1;
        }
    }

#pragma unroll
    for (int mf = 0; mf < 4; mf++) {
#pragma unroll
        for (int nf = 0; nf < 4; nf++) {
            float* cp = C + (size_t)(bm + wm * 64 + mf * 16 + g) * DM
                          + bn + wn * 32 + nf * 8 + tg * 2;
            *(float2*)cp = make_float2(acc[mf][nf][0], acc[mf][nf][1]);
            *(float2*)(cp + 8 * DM) = make_float2(acc[mf][nf][2], acc[mf][nf][3]);
        }
    }
}

// ---------------------------------------------------------------------------
// Tensor-core flash attention (TF32 mma, fp32 softmax/accum).
// One block = (b*H+h, 64 q-rows). 128 threads = 4 warps; warp w owns q rows
// [w*16, w*16+16). K and V tiles stored NATURAL [kv][d] in smem:
//   - S = Q@K^T: B-frag [n=kv][k=d] == K natural (conflict-free)
//   - P@V:      B-frag b0 = V[kv=8ks+tg][d=8nf+g] (2-way conflicts, ok)
// Q fragments hoisted into registers for the whole kv loop. Softmax (m,l)
// kept in registers replicated per quad. P goes through a warp-private smem
// strip (only __syncwarp between store and A-frag reload).
// ---------------------------------------------------------------------------
#define AP 68   // smem row pitch (floats)

__global__ __launch_bounds__(128)
void attn_mma_kernel(const float* __restrict__ Q,
                     const float* __restrict__ K,
                     const float* __restrict__ V,
                     float* __restrict__ ctx)
{
    const int bh = blockIdx.x;
    const int b  = bh / HH;
    const int h  = bh % HH;
    const int q0 = blockIdx.y * 64;

    extern __shared__ float sm[];
    float* Qs = sm;                  // [64][AP] natural q x d (tf32, pre-scaled)
    float* Ks = Qs + 64 * AP;        // [64][AP] natural kv x d (tf32)
    float* Vs = Ks + 64 * AP;        // [64][AP] natural kv x d (tf32)
    float* Ps = Vs + 64 * AP;        // [64][AP] q x kv (tf32)

    const int tid  = threadIdx.x;
    const int lane = tid & 31;
    const int warp = tid >> 5;       // 0..3
    const int wq   = warp * 16;
    const int g    = lane >> 2;      // 0..7
    const int tg   = lane & 3;       // 0..3

    const int lc = tid & 63;         // load column (feature)
    const int lr = tid >> 6;         // load row phase 0..1

    const float* Qbase = Q + ((size_t)b * SEQ + q0) * DM + h * DKH;
    const float* Kbase = K + (size_t)b * SEQ * DM + h * DKH;
    const float* Vbase = V + (size_t)b * SEQ * DM + h * DKH;

    // Load Q tile (scaled by 1/sqrt(64), tf32-rounded)
#pragma unroll
    for (int r = lr; r < 64; r += 2)
        Qs[r * AP + lc] = f2tf32(Qbase[(size_t)r * DM + lc] * 0.125f);
    __syncthreads();

    // Hoist Q A-fragments into registers (reused by every kv tile)
    uint32_t qa[8][4];
#pragma unroll
    for (int ks = 0; ks < 8; ks++) {
        const float* p0 = &Qs[(wq + g) * AP + ks * 8 + tg];
        const float* p1 = &Qs[(wq + g + 8) * AP + ks * 8 + tg];
        qa[ks][0] = __float_as_uint(p0[0]);
        qa[ks][1] = __float_as_uint(p1[0]);
        qa[ks][2] = __float_as_uint(p0[4]);
        qa[ks][3] = __float_as_uint(p1[4]);
    }

    float m_r[2] = {-INFINITY, -INFINITY};
    float l_r[2] = {0.f, 0.f};
    float Oacc[8][4];
#pragma unroll
    for (int nf = 0; nf < 8; nf++)
#pragma unroll
        for (int c = 0; c < 4; c++) Oacc[nf][c] = 0.f;

    for (int kt = 0; kt < SEQ; kt += 64) {
        __syncthreads();   // previous iteration's Ks/Vs reads done
        // Load K, V tiles (natural layout, tf32)
#pragma unroll
        for (int r = lr; r < 64; r += 2) {
            Ks[r * AP + lc] = f2tf32(Kbase[(size_t)(kt + r) * DM + lc]);
            Vs[r * AP + lc] = f2tf32(Vbase[(size_t)(kt + r) * DM + lc]);
        }
        __syncthreads();

        // ---- S = Q @ K^T (warp: 16 x 64) ----
        float sacc[8][4];
#pragma unroll
        for (int nf = 0; nf < 8; nf++)
#pragma unroll
            for (int c = 0; c < 4; c++) sacc[nf][c] = 0.f;

#pragma unroll
        for (int ks = 0; ks < 8; ks++) {
#pragma unroll
            for (int nf = 0; nf < 8; nf++) {
                const float* p = &Ks[(nf * 8 + g) * AP + ks * 8 + tg];
                uint32_t bf[2] = {__float_as_uint(p[0]), __float_as_uint(p[4])};
                mma_tf32(sacc[nf], qa[ks], bf);
            }
        }

        // ---- online softmax (rows g and g+8 of this warp's 16) ----
        float mx0 = -INFINITY, mx1 = -INFINITY;
#pragma unroll
        for (int nf = 0; nf < 8; nf++) {
            mx0 = fmaxf(mx0, fmaxf(sacc[nf][0], sacc[nf][1]));
            mx1 = fmaxf(mx1, fmaxf(sacc[nf][2], sacc[nf][3]));
        }
        mx0 = fmaxf(mx0, __shfl_xor_sync(0xffffffffu, mx0, 1));
        mx0 = fmaxf(mx0, __shfl_xor_sync(0xffffffffu, mx0, 2));
        mx1 = fmaxf(mx1, __shfl_xor_sync(0xffffffffu, mx1, 1));
        mx1 = fmaxf(mx1, __shfl_xor_sync(0xffffffffu, mx1, 2));

        const float mn0 = fmaxf(m_r[0], mx0);
        const float mn1 = fmaxf(m_r[1], mx1);
        const float al0 = __expf(m_r[0] - mn0);
        const float al1 = __expf(m_r[1] - mn1);

        float s0 = 0.f, s1 = 0.f;
#pragma unroll
        for (int nf = 0; nf < 8; nf++) {
            float p0 = __expf(sacc[nf][0] - mn0);
            float p1 = __expf(sacc[nf][1] - mn0);
            float p2 = __expf(sacc[nf][2] - mn1);
            float p3 = __expf(sacc[nf][3] - mn1);
            sacc[nf][0] = p0; sacc[nf][1] = p1;
            sacc[nf][2] = p2; sacc[nf][3] = p3;
            s0 += p0 + p1;
            s1 += p2 + p3;
        }
        s0 += __shfl_xor_sync(0xffffffffu, s0, 1);
        s0 += __shfl_xor_sync(0xffffffffu, s0, 2);
        s1 += __shfl_xor_sync(0xffffffffu, s1, 1);
        s1 += __shfl_xor_sync(0xffffffffu, s1, 2);

        m_r[0] = mn0; m_r[1] = mn1;
        l_r[0] = l_r[0] * al0 + s0;
        l_r[1] = l_r[1] * al1 + s1;

#pragma unroll
        for (int nf = 0; nf < 8; nf++) {
            Oacc[nf][0] *= al0; Oacc[nf][1] *= al0;
            Oacc[nf][2] *= al1; Oacc[nf][3] *= al1;
        }

        // ---- P -> warp-private smem (tf32) ----
#pragma unroll
        for (int nf = 0; nf < 8; nf++) {
            *(float2*)&Ps[(wq + g) * AP + nf * 8 + tg * 2] =
                make_float2(f2tf32(sacc[nf][0]), f2tf32(sacc[nf][1]));
            *(float2*)&Ps[(wq + g + 8) * AP + nf * 8 + tg * 2] =
                make_float2(f2tf32(sacc[nf][2]), f2tf32(sacc[nf][3]));
        }
        __syncwarp();

        // ---- O += P @ V (warp: 16 x 64, k = kv) ----
#pragma unroll
        for (int ks = 0; ks < 8; ks++) {
            uint32_t af[4];
            const float* p0 = &Ps[(wq + g) * AP + ks * 8 + tg];
            const float* p1 = &Ps[(wq + g + 8) * AP + ks * 8 + tg];
            af[0] = __float_as_uint(p0[0]);
            af[1] = __float_as_uint(p1[0]);
            af[2] = __float_as_uint(p0[4]);
            af[3] = __float_as_uint(p1[4]);
#pragma unroll
            for (int nf = 0; nf < 8; nf++) {
                uint32_t bf[2] = {
                    __float_as_uint(Vs[(ks * 8 + tg) * AP + nf * 8 + g]),
                    __float_as_uint(Vs[(ks * 8 + tg + 4) * AP + nf * 8 + g])
                };
                mma_tf32(Oacc[nf], af, bf);
            }
        }
    }

    // ---- epilogue: normalize and store ----
    const float inv0 = 1.f / l_r[0];
    const float inv1 = 1.f / l_r[1];
    float* out = ctx + ((size_t)b * SEQ + q0 + wq) * DM + h * DKH;
#pragma unroll
    for (int nf = 0; nf < 8; nf++) {
        *(float2*)&out[(size_t)g * DM + nf * 8 + tg * 2] =
            make_float2(Oacc[nf][0] * inv0, Oacc[nf][1] * inv0);
        *(float2*)&out[(size_t)(g + 8) * DM + nf * 8 + tg * 2] =
            make_float2(Oacc[nf][2] * inv1, Oacc[nf][3] * inv1);
    }
}

// ---------------------------------------------------------------------------
// Launch
// ---------------------------------------------------------------------------
extern "C" void kernel_launch(void* const* d_in, const int* in_sizes, int n_in,
                              void* d_out, int out_size)
{
    (void)in_sizes; (void)n_in; (void)out_size;
    const float* q  = (const float*)d_in[0];
    const float* k  = (const float*)d_in[1];
    const float* v  = (const float*)d_in[2];
    const float* Wq = (const float*)d_in[3];
    const float* Wk = (const float*)d_in[4];
    const float* Wv = (const float*)d_in[5];
    const float* Wo = (const float*)d_in[6];
    float* out = (float*)d_out;

    float *gQ, *gK, *gV, *gC;
    cudaGetSymbolAddress((void**)&gQ, g_Q);
    cudaGetSymbolAddress((void**)&gK, g_K);
    cudaGetSymbolAddress((void**)&gV, g_V);
    cudaGetSymbolAddress((void**)&gC, g_ctx);

    const int attn_smem = 4 * 64 * AP * (int)sizeof(float);  // 69632 B
    static bool attr_set = false;
    if (!attr_set) {
        cudaFuncSetAttribute(attn_mma_kernel,
                             cudaFuncAttributeMaxDynamicSharedMemorySize,
                             attn_smem);
        attr_set = true;
    }

    dim3 ggrid(DM / 128, MTOT / 128);   // (8, 64)
    gemm_tf32_kernel<<<ggrid, 256>>>(q, Wq, gQ);
    gemm_tf32_kernel<<<ggrid, 256>>>(k, Wk, gK);
    gemm_tf32_kernel<<<ggrid, 256>>>(v, Wv, gV);

    dim3 agrid(BATCH * HH, SEQ / 64);   // (64, 32)
    attn_mma_kernel<<<agrid, 128, attn_smem>>>(gQ, gK, gV, gC);

    gemm_tf32_kernel<<<ggrid, 256>>>(gC, Wo, out);
}

// round 4
// speedup vs baseline: 3.0985x; 1.0739x over previous
#include <cuda_runtime.h>
#include <math.h>
#include <stdint.h>

// Problem constants (fixed by the reference)
#define DM    1024
#define HH    16
#define DKH   64
#define BATCH 4
#define SEQ   2048
#define MTOT  (BATCH * SEQ)   // 8192

// ---------------------------------------------------------------------------
// Scratch (no allocations allowed -> __device__ globals)
// ---------------------------------------------------------------------------
__device__ __align__(128) float g_Q[(size_t)MTOT * DM];
__device__ __align__(128) float g_K[(size_t)MTOT * DM];
__device__ __align__(128) float g_V[(size_t)MTOT * DM];
__device__ __align__(128) float g_ctx[(size_t)MTOT * DM];

// ---------------------------------------------------------------------------
// TF32 helpers
// ---------------------------------------------------------------------------
__device__ __forceinline__ float f2tf32(float x) {
    uint32_t r;
    asm("cvt.rna.tf32.f32 %0, %1;" : "=r"(r) : "f"(x));
    return __uint_as_float(r);
}

__device__ __forceinline__ void mma_tf32(float (&d)[4],
                                         const uint32_t (&a)[4],
                                         const uint32_t (&b)[2]) {
    asm volatile(
        "mma.sync.aligned.m16n8k8.row.col.f32.tf32.tf32.f32 "
        "{%0,%1,%2,%3}, {%4,%5,%6,%7}, {%8,%9}, {%0,%1,%2,%3};"
        : "+f"(d[0]), "+f"(d[1]), "+f"(d[2]), "+f"(d[3])
        : "r"(a[0]), "r"(a[1]), "r"(a[2]), "r"(a[3]),
          "r"(b[0]), "r"(b[1]));
}

__device__ __forceinline__ void cp16(uint32_t dst_smem, const void* src) {
    asm volatile("cp.async.ca.shared.global [%0], [%1], 16;"
                 :: "r"(dst_smem), "l"(src));
}
__device__ __forceinline__ void cp_commit() {
    asm volatile("cp.async.commit_group;");
}
template <int N>
__device__ __forceinline__ void cp_wait() {
    asm volatile("cp.async.wait_group %0;" :: "n"(N));
}

// ---------------------------------------------------------------------------
// TF32 tensor-core GEMM NT: C[M,N] = A[M,K] * B[N,K]^T  (y = x @ W.T)
// MODE epilogue: 0 = plain f32 store, 1 = tf32-rounded store,
//                2 = tf32-rounded store of 0.125*acc (Q projection).
// ---------------------------------------------------------------------------
#define GP 20   // smem row pitch in floats (16 + 4 pad)

template <int MODE>
__global__ __launch_bounds__(256)
void gemm_tf32_kernel(const float* __restrict__ A,
                      const float* __restrict__ B,
                      float* __restrict__ C)
{
    __shared__ float As[2][128 * GP];
    __shared__ float Bs[2][128 * GP];

    const int tid = threadIdx.x;
    const int bm = blockIdx.y * 128;
    const int bn = blockIdx.x * 128;

    const int lane = tid & 31;
    const int wid  = tid >> 5;
    const int wm   = wid >> 2;
    const int wn   = wid & 3;
    const int g    = lane >> 2;
    const int tg   = lane & 3;

    const int m0  = tid >> 2;
    const int kq4 = (tid & 3) * 4;

    float4 pa[2], pb[2];

    float acc[4][4][4];
#pragma unroll
    for (int i = 0; i < 4; i++)
#pragma unroll
        for (int j = 0; j < 4; j++)
#pragma unroll
            for (int c = 0; c < 4; c++) acc[i][j][c] = 0.f;

    auto fetch = [&](int k0) {
#pragma unroll
        for (int i = 0; i < 2; i++) {
            int m = m0 + i * 64;
            pa[i] = *(const float4*)(A + (size_t)(bm + m) * DM + k0 + kq4);
            pb[i] = *(const float4*)(B + (size_t)(bn + m) * DM + k0 + kq4);
        }
    };
    auto stash = [&](int buf) {
#pragma unroll
        for (int i = 0; i < 2; i++) {
            int m = m0 + i * 64;
            float* a = &As[buf][m * GP + kq4];
            float* b = &Bs[buf][m * GP + kq4];
            a[0] = f2tf32(pa[i].x); a[1] = f2tf32(pa[i].y);
            a[2] = f2tf32(pa[i].z); a[3] = f2tf32(pa[i].w);
            b[0] = f2tf32(pb[i].x); b[1] = f2tf32(pb[i].y);
            b[2] = f2tf32(pb[i].z); b[3] = f2tf32(pb[i].w);
        }
    };

    fetch(0);
    stash(0);
    __syncthreads();

    int buf = 0;
    for (int k0 = 0; k0 < DM; k0 += 16) {
        const bool more = (k0 + 16 < DM);
        if (more) fetch(k0 + 16);

        const float* as = As[buf];
        const float* bs = Bs[buf];
#pragma unroll
        for (int ks = 0; ks < 16; ks += 8) {
            uint32_t af[4][4];
            uint32_t bf[4][2];
#pragma unroll
            for (int mf = 0; mf < 4; mf++) {
                const float* p = &as[(wm * 64 + mf * 16 + g) * GP + ks + tg];
                af[mf][0] = __float_as_uint(p[0]);
                af[mf][1] = __float_as_uint(p[8 * GP]);
                af[mf][2] = __float_as_uint(p[4]);
                af[mf][3] = __float_as_uint(p[8 * GP + 4]);
            }
#pragma unroll
            for (int nf = 0; nf < 4; nf++) {
                const float* p = &bs[(wn * 32 + nf * 8 + g) * GP + ks + tg];
                bf[nf][0] = __float_as_uint(p[0]);
                bf[nf][1] = __float_as_uint(p[4]);
            }
#pragma unroll
            for (int mf = 0; mf < 4; mf++)
#pragma unroll
                for (int nf = 0; nf < 4; nf++)
                    mma_tf32(acc[mf][nf], af[mf], bf[nf]);
        }

        if (more) {
            stash(buf ^ 1);
            __syncthreads();
            buf ^= 1;
        }
    }

    auto ep = [&](float x) -> float {
        if (MODE == 0) return x;
        if (MODE == 1) return f2tf32(x);
        return f2tf32(x * 0.125f);
    };

#pragma unroll
    for (int mf = 0; mf < 4; mf++) {
#pragma unroll
        for (int nf = 0; nf < 4; nf++) {
            float* cp = C + (size_t)(bm + wm * 64 + mf * 16 + g) * DM
                          + bn + wn * 32 + nf * 8 + tg * 2;
            *(float2*)cp = make_float2(ep(acc[mf][nf][0]), ep(acc[mf][nf][1]));
            *(float2*)(cp + 8 * DM) = make_float2(ep(acc[mf][nf][2]), ep(acc[mf][nf][3]));
        }
    }
}

// ---------------------------------------------------------------------------
// Tensor-core flash attention v2.
// Block = (b*H+h, 128 q-rows), 128 threads = 4 warps, each warp 32 q rows
// (two m16 fragments sharing every B-fragment load -> ~1.4 LDS per MMA).
// Inputs are PRE-tf32 (Q also pre-scaled) from GEMM epilogues, so K/V tiles
// stream via cp.async (16B) with double buffering -> no cvt, no LDG->STS.
// Pitches: K=68 (S-frag conflict-free), V=72 (PV-frag conflict-free).
// ---------------------------------------------------------------------------
#define KP 68
#define VP 72
#define PP 68
#define QTILE 128
#define NKV   (SEQ / 64)   // 32 kv tiles

__global__ __launch_bounds__(128)
void attn_mma2_kernel(const float* __restrict__ Q,
                      const float* __restrict__ K,
                      const float* __restrict__ V,
                      float* __restrict__ ctx)
{
    const int bh = blockIdx.x;
    const int b  = bh / HH;
    const int h  = bh % HH;
    const int q0 = blockIdx.y * QTILE;

    extern __shared__ float sm[];
    float* Ks = sm;                         // [2][64*KP]
    float* Vs = Ks + 2 * 64 * KP;           // [2][64*VP]
    float* Ps = Vs + 2 * 64 * VP;           // [128][PP]

    const int tid  = threadIdx.x;
    const int lane = tid & 31;
    const int warp = tid >> 5;
    const int wq   = warp * 32;
    const int g    = lane >> 2;
    const int tg   = lane & 3;

    const float* Kbase = K + (size_t)b * SEQ * DM + h * DKH;
    const float* Vbase = V + (size_t)b * SEQ * DM + h * DKH;

    const uint32_t ks_smem = (uint32_t)__cvta_generic_to_shared(Ks);
    const uint32_t vs_smem = (uint32_t)__cvta_generic_to_shared(Vs);

    // cooperative tile loader: 64 rows x 16 float4 per array, 128 threads -> 8 each
    auto prefetch = [&](int t, int buf) {
#pragma unroll
        for (int i = 0; i < 8; i++) {
            int idx = tid + i * 128;
            int row = idx >> 4;
            int c4  = (idx & 15) * 4;
            const float* ks_src = Kbase + (size_t)(t * 64 + row) * DM + c4;
            const float* vs_src = Vbase + (size_t)(t * 64 + row) * DM + c4;
            cp16(ks_smem + (buf * 64 * KP + row * KP + c4) * 4, ks_src);
            cp16(vs_smem + (buf * 64 * VP + row * VP + c4) * 4, vs_src);
        }
        cp_commit();
    };

    // ---- hoist Q fragments (pre-scaled, pre-tf32) straight from gmem ----
    uint32_t qa[2][8][4];
    {
        const float* Qb = Q + ((size_t)b * SEQ + q0 + wq) * DM + h * DKH;
#pragma unroll
        for (int mf = 0; mf < 2; mf++)
#pragma unroll
            for (int ks = 0; ks < 8; ks++) {
                const float* r0 = Qb + (size_t)(mf * 16 + g) * DM + ks * 8 + tg;
                const float* r1 = r0 + (size_t)8 * DM;
                qa[mf][ks][0] = __float_as_uint(r0[0]);
                qa[mf][ks][1] = __float_as_uint(r1[0]);
                qa[mf][ks][2] = __float_as_uint(r0[4]);
                qa[mf][ks][3] = __float_as_uint(r1[4]);
            }
    }

    prefetch(0, 0);

    float m_r[2][2], l_r[2][2];
    float Oacc[2][8][4];
#pragma unroll
    for (int mf = 0; mf < 2; mf++) {
        m_r[mf][0] = -INFINITY; m_r[mf][1] = -INFINITY;
        l_r[mf][0] = 0.f;       l_r[mf][1] = 0.f;
#pragma unroll
        for (int nf = 0; nf < 8; nf++)
#pragma unroll
            for (int c = 0; c < 4; c++) Oacc[mf][nf][c] = 0.f;
    }

    int buf = 0;
    for (int t = 0; t < NKV; t++) {
        if (t + 1 < NKV) prefetch(t + 1, buf ^ 1);
        else             cp_commit();
        cp_wait<1>();
        __syncthreads();

        const float* kt = Ks + buf * 64 * KP;
        const float* vt = Vs + buf * 64 * VP;

        // ---- S = Q @ K^T : each warp 32x64, 1 B-frag load per 2 MMAs ----
        float sacc[2][8][4];
#pragma unroll
        for (int mf = 0; mf < 2; mf++)
#pragma unroll
            for (int nf = 0; nf < 8; nf++)
#pragma unroll
                for (int c = 0; c < 4; c++) sacc[mf][nf][c] = 0.f;

#pragma unroll
        for (int ks = 0; ks < 8; ks++) {
#pragma unroll
            for (int nf = 0; nf < 8; nf++) {
                const float* p = &kt[(nf * 8 + g) * KP + ks * 8 + tg];
                uint32_t bf[2] = {__float_as_uint(p[0]), __float_as_uint(p[4])};
                mma_tf32(sacc[0][nf], qa[0][ks], bf);
                mma_tf32(sacc[1][nf], qa[1][ks], bf);
            }
        }

        // ---- online softmax + P stash (per m-fragment) ----
#pragma unroll
        for (int mf = 0; mf < 2; mf++) {
            float mx0 = -INFINITY, mx1 = -INFINITY;
#pragma unroll
            for (int nf = 0; nf < 8; nf++) {
                mx0 = fmaxf(mx0, fmaxf(sacc[mf][nf][0], sacc[mf][nf][1]));
                mx1 = fmaxf(mx1, fmaxf(sacc[mf][nf][2], sacc[mf][nf][3]));
            }
            mx0 = fmaxf(mx0, __shfl_xor_sync(0xffffffffu, mx0, 1));
            mx0 = fmaxf(mx0, __shfl_xor_sync(0xffffffffu, mx0, 2));
            mx1 = fmaxf(mx1, __shfl_xor_sync(0xffffffffu, mx1, 1));
            mx1 = fmaxf(mx1, __shfl_xor_sync(0xffffffffu, mx1, 2));

            const float mn0 = fmaxf(m_r[mf][0], mx0);
            const float mn1 = fmaxf(m_r[mf][1], mx1);
            const float al0 = __expf(m_r[mf][0] - mn0);
            const float al1 = __expf(m_r[mf][1] - mn1);

            float s0 = 0.f, s1 = 0.f;
            float* prow0 = &Ps[(wq + mf * 16 + g) * PP];
            float* prow1 = prow0 + 8 * PP;
#pragma unroll
            for (int nf = 0; nf < 8; nf++) {
                float p0 = __expf(sacc[mf][nf][0] - mn0);
                float p1 = __expf(sacc[mf][nf][1] - mn0);
                float p2 = __expf(sacc[mf][nf][2] - mn1);
                float p3 = __expf(sacc[mf][nf][3] - mn1);
                s0 += p0 + p1;
                s1 += p2 + p3;
                *(float2*)&prow0[nf * 8 + tg * 2] = make_float2(f2tf32(p0), f2tf32(p1));
                *(float2*)&prow1[nf * 8 + tg * 2] = make_float2(f2tf32(p2), f2tf32(p3));
            }
            s0 += __shfl_xor_sync(0xffffffffu, s0, 1);
            s0 += __shfl_xor_sync(0xffffffffu, s0, 2);
            s1 += __shfl_xor_sync(0xffffffffu, s1, 1);
            s1 += __shfl_xor_sync(0xffffffffu, s1, 2);

            m_r[mf][0] = mn0; m_r[mf][1] = mn1;
            l_r[mf][0] = l_r[mf][0] * al0 + s0;
            l_r[mf][1] = l_r[mf][1] * al1 + s1;

#pragma unroll
            for (int nf = 0; nf < 8; nf++) {
                Oacc[mf][nf][0] *= al0; Oacc[mf][nf][1] *= al0;
                Oacc[mf][nf][2] *= al1; Oacc[mf][nf][3] *= al1;
            }
        }
        __syncwarp();

        // ---- O += P @ V : V B-frag load shared by 2 MMAs ----
#pragma unroll
        for (int ks = 0; ks < 8; ks++) {
            uint32_t af[2][4];
#pragma unroll
            for (int mf = 0; mf < 2; mf++) {
                const float* p0 = &Ps[(wq + mf * 16 + g) * PP + ks * 8 + tg];
                const float* p1 = p0 + 8 * PP;
                af[mf][0] = __float_as_uint(p0[0]);
                af[mf][1] = __float_as_uint(p1[0]);
                af[mf][2] = __float_as_uint(p0[4]);
                af[mf][3] = __float_as_uint(p1[4]);
            }
#pragma unroll
            for (int nf = 0; nf < 8; nf++) {
                uint32_t bf[2] = {
                    __float_as_uint(vt[(ks * 8 + tg) * VP + nf * 8 + g]),
                    __float_as_uint(vt[(ks * 8 + tg + 4) * VP + nf * 8 + g])
                };
                mma_tf32(Oacc[0][nf], af[0], bf);
                mma_tf32(Oacc[1][nf], af[1], bf);
            }
        }

        __syncthreads();
        buf ^= 1;
    }

    // ---- epilogue ----
#pragma unroll
    for (int mf = 0; mf < 2; mf++) {
        const float inv0 = 1.f / l_r[mf][0];
        const float inv1 = 1.f / l_r[mf][1];
        float* out = ctx + ((size_t)b * SEQ + q0 + wq + mf * 16) * DM + h * DKH;
#pragma unroll
        for (int nf = 0; nf < 8; nf++) {
            *(float2*)&out[(size_t)g * DM + nf * 8 + tg * 2] =
                make_float2(Oacc[mf][nf][0] * inv0, Oacc[mf][nf][1] * inv0);
            *(float2*)&out[(size_t)(g + 8) * DM + nf * 8 + tg * 2] =
                make_float2(Oacc[mf][nf][2] * inv1, Oacc[mf][nf][3] * inv1);
        }
    }
}

// ---------------------------------------------------------------------------
// Launch
// ---------------------------------------------------------------------------
extern "C" void kernel_launch(void* const* d_in, const int* in_sizes, int n_in,
                              void* d_out, int out_size)
{
    (void)in_sizes; (void)n_in; (void)out_size;
    const float* q  = (const float*)d_in[0];
    const float* k  = (const float*)d_in[1];
    const float* v  = (const float*)d_in[2];
    const float* Wq = (const float*)d_in[3];
    const float* Wk = (const float*)d_in[4];
    const float* Wv = (const float*)d_in[5];
    const float* Wo = (const float*)d_in[6];
    float* out = (float*)d_out;

    float *gQ, *gK, *gV, *gC;
    cudaGetSymbolAddress((void**)&gQ, g_Q);
    cudaGetSymbolAddress((void**)&gK, g_K);
    cudaGetSymbolAddress((void**)&gV, g_V);
    cudaGetSymbolAddress((void**)&gC, g_ctx);

    const int attn_smem = (2 * 64 * KP + 2 * 64 * VP + QTILE * PP) * (int)sizeof(float);
    static bool attr_set = false;
    if (!attr_set) {
        cudaFuncSetAttribute(attn_mma2_kernel,
                             cudaFuncAttributeMaxDynamicSharedMemorySize,
                             attn_smem);
        attr_set = true;
    }

    dim3 ggrid(DM / 128, MTOT / 128);   // (8, 64)
    gemm_tf32_kernel<2><<<ggrid, 256>>>(q, Wq, gQ);   // Q: tf32 + 1/sqrt(dk)
    gemm_tf32_kernel<1><<<ggrid, 256>>>(k, Wk, gK);   // K: tf32
    gemm_tf32_kernel<1><<<ggrid, 256>>>(v, Wv, gV);   // V: tf32

    dim3 agrid(BATCH * HH, SEQ / QTILE);   // (64, 16)
    attn_mma2_kernel<<<agrid, 128, attn_smem>>>(gQ, gK, gV, gC);

    gemm_tf32_kernel<0><<<ggrid, 256>>>(gC, Wo, out); // plain f32 out
}

// round 5
// speedup vs baseline: 3.5831x; 1.1564x over previous
#include <cuda_runtime.h>
#include <math.h>
#include <stdint.h>

// Problem constants (fixed by the reference)
#define DM    1024
#define HH    16
#define DKH   64
#define BATCH 4
#define SEQ   2048
#define MTOT  (BATCH * SEQ)   // 8192

// ---------------------------------------------------------------------------
// Scratch (no allocations allowed -> __device__ globals)
// ---------------------------------------------------------------------------
__device__ __align__(128) float g_Q[(size_t)MTOT * DM];
__device__ __align__(128) float g_K[(size_t)MTOT * DM];
__device__ __align__(128) float g_V[(size_t)MTOT * DM];
__device__ __align__(128) float g_ctx[(size_t)MTOT * DM];

// ---------------------------------------------------------------------------
// TF32 helpers
// ---------------------------------------------------------------------------
__device__ __forceinline__ float f2tf32(float x) {
    uint32_t r;
    asm("cvt.rna.tf32.f32 %0, %1;" : "=r"(r) : "f"(x));
    return __uint_as_float(r);
}

__device__ __forceinline__ void mma_tf32(float (&d)[4],
                                         const uint32_t (&a)[4],
                                         const uint32_t (&b)[2]) {
    asm volatile(
        "mma.sync.aligned.m16n8k8.row.col.f32.tf32.tf32.f32 "
        "{%0,%1,%2,%3}, {%4,%5,%6,%7}, {%8,%9}, {%0,%1,%2,%3};"
        : "+f"(d[0]), "+f"(d[1]), "+f"(d[2]), "+f"(d[3])
        : "r"(a[0]), "r"(a[1]), "r"(a[2]), "r"(a[3]),
          "r"(b[0]), "r"(b[1]));
}

__device__ __forceinline__ void cp16(uint32_t dst_smem, const void* src) {
    asm volatile("cp.async.cg.shared.global [%0], [%1], 16;"
                 :: "r"(dst_smem), "l"(src));
}
__device__ __forceinline__ void cp_commit() {
    asm volatile("cp.async.commit_group;");
}
template <int N>
__device__ __forceinline__ void cp_wait() {
    asm volatile("cp.async.wait_group %0;" :: "n"(N));
}

// ---------------------------------------------------------------------------
// TF32 tensor-core GEMM NT: C[M,N] = A[M,K] * B[N,K]^T  (y = x @ W.T)
// MODE epilogue: 0 = plain f32 store, 1 = tf32-rounded store,
//                2 = tf32-rounded store of 0.125*acc (Q projection).
// (unchanged from round 4 — verified correct)
// ---------------------------------------------------------------------------
#define GP 20   // smem row pitch in floats (16 + 4 pad)

template <int MODE>
__global__ __launch_bounds__(256)
void gemm_tf32_kernel(const float* __restrict__ A,
                      const float* __restrict__ B,
                      float* __restrict__ C)
{
    __shared__ float As[2][128 * GP];
    __shared__ float Bs[2][128 * GP];

    const int tid = threadIdx.x;
    const int bm = blockIdx.y * 128;
    const int bn = blockIdx.x * 128;

    const int lane = tid & 31;
    const int wid  = tid >> 5;
    const int wm   = wid >> 2;
    const int wn   = wid & 3;
    const int g    = lane >> 2;
    const int tg   = lane & 3;

    const int m0  = tid >> 2;
    const int kq4 = (tid & 3) * 4;

    float4 pa[2], pb[2];

    float acc[4][4][4];
#pragma unroll
    for (int i = 0; i < 4; i++)
#pragma unroll
        for (int j = 0; j < 4; j++)
#pragma unroll
            for (int c = 0; c < 4; c++) acc[i][j][c] = 0.f;

    auto fetch = [&](int k0) {
#pragma unroll
        for (int i = 0; i < 2; i++) {
            int m = m0 + i * 64;
            pa[i] = *(const float4*)(A + (size_t)(bm + m) * DM + k0 + kq4);
            pb[i] = *(const float4*)(B + (size_t)(bn + m) * DM + k0 + kq4);
        }
    };
    auto stash = [&](int buf) {
#pragma unroll
        for (int i = 0; i < 2; i++) {
            int m = m0 + i * 64;
            float* a = &As[buf][m * GP + kq4];
            float* b = &Bs[buf][m * GP + kq4];
            a[0] = f2tf32(pa[i].x); a[1] = f2tf32(pa[i].y);
            a[2] = f2tf32(pa[i].z); a[3] = f2tf32(pa[i].w);
            b[0] = f2tf32(pb[i].x); b[1] = f2tf32(pb[i].y);
            b[2] = f2tf32(pb[i].z); b[3] = f2tf32(pb[i].w);
        }
    };

    fetch(0);
    stash(0);
    __syncthreads();

    int buf = 0;
    for (int k0 = 0; k0 < DM; k0 += 16) {
        const bool more = (k0 + 16 < DM);
        if (more) fetch(k0 + 16);

        const float* as = As[buf];
        const float* bs = Bs[buf];
#pragma unroll
        for (int ks = 0; ks < 16; ks += 8) {
            uint32_t af[4][4];
            uint32_t bf[4][2];
#pragma unroll
            for (int mf = 0; mf < 4; mf++) {
                const float* p = &as[(wm * 64 + mf * 16 + g) * GP + ks + tg];
                af[mf][0] = __float_as_uint(p[0]);
                af[mf][1] = __float_as_uint(p[8 * GP]);
                af[mf][2] = __float_as_uint(p[4]);
                af[mf][3] = __float_as_uint(p[8 * GP + 4]);
            }
#pragma unroll
            for (int nf = 0; nf < 4; nf++) {
                const float* p = &bs[(wn * 32 + nf * 8 + g) * GP + ks + tg];
                bf[nf][0] = __float_as_uint(p[0]);
                bf[nf][1] = __float_as_uint(p[4]);
            }
#pragma unroll
            for (int mf = 0; mf < 4; mf++)
#pragma unroll
                for (int nf = 0; nf < 4; nf++)
                    mma_tf32(acc[mf][nf], af[mf], bf[nf]);
        }

        if (more) {
            stash(buf ^ 1);
            __syncthreads();
            buf ^= 1;
        }
    }

    auto ep = [&](float x) -> float {
        if (MODE == 0) return x;
        if (MODE == 1) return f2tf32(x);
        return f2tf32(x * 0.125f);
    };

#pragma unroll
    for (int mf = 0; mf < 4; mf++) {
#pragma unroll
        for (int nf = 0; nf < 4; nf++) {
            float* cp = C + (size_t)(bm + wm * 64 + mf * 16 + g) * DM
                          + bn + wn * 32 + nf * 8 + tg * 2;
            *(float2*)cp = make_float2(ep(acc[mf][nf][0]), ep(acc[mf][nf][1]));
            *(float2*)(cp + 8 * DM) = make_float2(ep(acc[mf][nf][2]), ep(acc[mf][nf][3]));
        }
    }
}

// ---------------------------------------------------------------------------
// Tensor-core flash attention v3.
// Block = (b*H+h, 128 q-rows), 128 threads = 4 warps, warp = 32 q rows
// (two m16 A-frags share every B-frag load). kv tile 64 processed in two
// 32-column chunks (sacc = 32 regs, online softmax per chunk). P never
// touches smem: C-frag -> A-frag via intra-quad shfl.idx (cols {2tg,2tg+1}
// -> {tg,tg+4} is a pure lane permutation). No spills (~200 regs).
// K/V stream via cp.async double buffering; inputs pre-tf32 (Q pre-scaled).
// ---------------------------------------------------------------------------
#define KP 68
#define VP 72
#define QTILE 128
#define NKV   (SEQ / 64)   // 32 kv tiles

__global__ __launch_bounds__(128)
void attn_mma3_kernel(const float* __restrict__ Q,
                      const float* __restrict__ K,
                      const float* __restrict__ V,
                      float* __restrict__ ctx)
{
    const int bh = blockIdx.x;
    const int b  = bh / HH;
    const int h  = bh % HH;
    const int q0 = blockIdx.y * QTILE;

    extern __shared__ float sm[];
    float* Ks = sm;                         // [2][64*KP]
    float* Vs = Ks + 2 * 64 * KP;           // [2][64*VP]

    const int tid  = threadIdx.x;
    const int lane = tid & 31;
    const int warp = tid >> 5;
    const int wq   = warp * 32;
    const int g    = lane >> 2;
    const int tg   = lane & 3;
    const int idx_lo = (lane & ~3) | (tg >> 1);   // shuffle sources
    const int idx_hi = idx_lo + 2;
    const bool odd = (tg & 1);

    const float* Kbase = K + (size_t)b * SEQ * DM + h * DKH;
    const float* Vbase = V + (size_t)b * SEQ * DM + h * DKH;

    const uint32_t ks_smem = (uint32_t)__cvta_generic_to_shared(Ks);
    const uint32_t vs_smem = (uint32_t)__cvta_generic_to_shared(Vs);

    // cooperative tile loader: 64 rows x 16 float4 per array, 128 threads -> 8 each
    auto prefetch = [&](int t, int buf) {
#pragma unroll
        for (int i = 0; i < 8; i++) {
            int idx = tid + i * 128;
            int row = idx >> 4;
            int c4  = (idx & 15) * 4;
            const float* ks_src = Kbase + (size_t)(t * 64 + row) * DM + c4;
            const float* vs_src = Vbase + (size_t)(t * 64 + row) * DM + c4;
            cp16(ks_smem + (buf * 64 * KP + row * KP + c4) * 4, ks_src);
            cp16(vs_smem + (buf * 64 * VP + row * VP + c4) * 4, vs_src);
        }
        cp_commit();
    };

    // ---- hoist Q fragments (pre-scaled, pre-tf32) straight from gmem ----
    uint32_t qa[2][8][4];
    {
        const float* Qb = Q + ((size_t)b * SEQ + q0 + wq) * DM + h * DKH;
#pragma unroll
        for (int mf = 0; mf < 2; mf++)
#pragma unroll
            for (int ks = 0; ks < 8; ks++) {
                const float* r0 = Qb + (size_t)(mf * 16 + g) * DM + ks * 8 + tg;
                const float* r1 = r0 + (size_t)8 * DM;
                qa[mf][ks][0] = __float_as_uint(r0[0]);
                qa[mf][ks][1] = __float_as_uint(r1[0]);
                qa[mf][ks][2] = __float_as_uint(r0[4]);
                qa[mf][ks][3] = __float_as_uint(r1[4]);
            }
    }

    prefetch(0, 0);

    float m_r[2][2], l_r[2][2];
    float Oacc[2][8][4];
#pragma unroll
    for (int mf = 0; mf < 2; mf++) {
        m_r[mf][0] = -INFINITY; m_r[mf][1] = -INFINITY;
        l_r[mf][0] = 0.f;       l_r[mf][1] = 0.f;
#pragma unroll
        for (int nf = 0; nf < 8; nf++)
#pragma unroll
            for (int c = 0; c < 4; c++) Oacc[mf][nf][c] = 0.f;
    }

    int buf = 0;
    for (int t = 0; t < NKV; t++) {
        if (t + 1 < NKV) prefetch(t + 1, buf ^ 1);
        else             cp_commit();
        cp_wait<1>();
        __syncthreads();

        const float* kt = Ks + buf * 64 * KP;
        const float* vt = Vs + buf * 64 * VP;

        // ---- two 32-column kv chunks ----
#pragma unroll
        for (int kc = 0; kc < 2; kc++) {
            // S = Q @ K^T for this chunk (warp: 32 q x 32 kv)
            float sacc[2][4][4];
#pragma unroll
            for (int mf = 0; mf < 2; mf++)
#pragma unroll
                for (int nf = 0; nf < 4; nf++)
#pragma unroll
                    for (int c = 0; c < 4; c++) sacc[mf][nf][c] = 0.f;

#pragma unroll
            for (int ks = 0; ks < 8; ks++) {
#pragma unroll
                for (int nf = 0; nf < 4; nf++) {
                    const float* p = &kt[(kc * 32 + nf * 8 + g) * KP + ks * 8 + tg];
                    uint32_t bf[2] = {__float_as_uint(p[0]), __float_as_uint(p[4])};
                    mma_tf32(sacc[0][nf], qa[0][ks], bf);
                    mma_tf32(sacc[1][nf], qa[1][ks], bf);
                }
            }

            // online softmax per m-fragment (rows g, g+8)
#pragma unroll
            for (int mf = 0; mf < 2; mf++) {
                float mx0 = -INFINITY, mx1 = -INFINITY;
#pragma unroll
                for (int nf = 0; nf < 4; nf++) {
                    mx0 = fmaxf(mx0, fmaxf(sacc[mf][nf][0], sacc[mf][nf][1]));
                    mx1 = fmaxf(mx1, fmaxf(sacc[mf][nf][2], sacc[mf][nf][3]));
                }
                mx0 = fmaxf(mx0, __shfl_xor_sync(0xffffffffu, mx0, 1));
                mx0 = fmaxf(mx0, __shfl_xor_sync(0xffffffffu, mx0, 2));
                mx1 = fmaxf(mx1, __shfl_xor_sync(0xffffffffu, mx1, 1));
                mx1 = fmaxf(mx1, __shfl_xor_sync(0xffffffffu, mx1, 2));

                const float mn0 = fmaxf(m_r[mf][0], mx0);
                const float mn1 = fmaxf(m_r[mf][1], mx1);
                const float al0 = __expf(m_r[mf][0] - mn0);
                const float al1 = __expf(m_r[mf][1] - mn1);

                float s0 = 0.f, s1 = 0.f;
#pragma unroll
                for (int nf = 0; nf < 4; nf++) {
                    float p0 = __expf(sacc[mf][nf][0] - mn0);
                    float p1 = __expf(sacc[mf][nf][1] - mn0);
                    float p2 = __expf(sacc[mf][nf][2] - mn1);
                    float p3 = __expf(sacc[mf][nf][3] - mn1);
                    sacc[mf][nf][0] = p0; sacc[mf][nf][1] = p1;
                    sacc[mf][nf][2] = p2; sacc[mf][nf][3] = p3;
                    s0 += p0 + p1;
                    s1 += p2 + p3;
                }
                s0 += __shfl_xor_sync(0xffffffffu, s0, 1);
                s0 += __shfl_xor_sync(0xffffffffu, s0, 2);
                s1 += __shfl_xor_sync(0xffffffffu, s1, 1);
                s1 += __shfl_xor_sync(0xffffffffu, s1, 2);

                m_r[mf][0] = mn0; m_r[mf][1] = mn1;
                l_r[mf][0] = l_r[mf][0] * al0 + s0;
                l_r[mf][1] = l_r[mf][1] * al1 + s1;

#pragma unroll
                for (int nf = 0; nf < 8; nf++) {
                    Oacc[mf][nf][0] *= al0; Oacc[mf][nf][1] *= al0;
                    Oacc[mf][nf][2] *= al1; Oacc[mf][nf][3] *= al1;
                }
            }

            // C-frag -> A-frag in registers (intra-quad shuffles), tf32-round
            uint32_t af[2][4][4];
#pragma unroll
            for (int mf = 0; mf < 2; mf++)
#pragma unroll
                for (int nf = 0; nf < 4; nf++) {
                    float v0l = __shfl_sync(0xffffffffu, sacc[mf][nf][0], idx_lo);
                    float v1l = __shfl_sync(0xffffffffu, sacc[mf][nf][1], idx_lo);
                    float v2l = __shfl_sync(0xffffffffu, sacc[mf][nf][2], idx_lo);
                    float v3l = __shfl_sync(0xffffffffu, sacc[mf][nf][3], idx_lo);
                    float v0h = __shfl_sync(0xffffffffu, sacc[mf][nf][0], idx_hi);
                    float v1h = __shfl_sync(0xffffffffu, sacc[mf][nf][1], idx_hi);
                    float v2h = __shfl_sync(0xffffffffu, sacc[mf][nf][2], idx_hi);
                    float v3h = __shfl_sync(0xffffffffu, sacc[mf][nf][3], idx_hi);
                    af[mf][nf][0] = __float_as_uint(f2tf32(odd ? v1l : v0l));
                    af[mf][nf][1] = __float_as_uint(f2tf32(odd ? v3l : v2l));
                    af[mf][nf][2] = __float_as_uint(f2tf32(odd ? v1h : v0h));
                    af[mf][nf][3] = __float_as_uint(f2tf32(odd ? v3h : v2h));
                }

            // O += P @ V for this chunk: k rows = kc*32 + ksl*8 + {tg, tg+4}
#pragma unroll
            for (int ksl = 0; ksl < 4; ksl++) {
#pragma unroll
                for (int nf = 0; nf < 8; nf++) {
                    uint32_t bf[2] = {
                        __float_as_uint(vt[(kc * 32 + ksl * 8 + tg) * VP + nf * 8 + g]),
                        __float_as_uint(vt[(kc * 32 + ksl * 8 + tg + 4) * VP + nf * 8 + g])
                    };
                    mma_tf32(Oacc[0][nf], af[0][ksl], bf);
                    mma_tf32(Oacc[1][nf], af[1][ksl], bf);
                }
            }
        }

        __syncthreads();
        buf ^= 1;
    }

    // ---- epilogue ----
#pragma unroll
    for (int mf = 0; mf < 2; mf++) {
        const float inv0 = 1.f / l_r[mf][0];
        const float inv1 = 1.f / l_r[mf][1];
        float* out = ctx + ((size_t)b * SEQ + q0 + wq + mf * 16) * DM + h * DKH;
#pragma unroll
        for (int nf = 0; nf < 8; nf++) {
            *(float2*)&out[(size_t)g * DM + nf * 8 + tg * 2] =
                make_float2(Oacc[mf][nf][0] * inv0, Oacc[mf][nf][1] * inv0);
            *(float2*)&out[(size_t)(g + 8) * DM + nf * 8 + tg * 2] =
                make_float2(Oacc[mf][nf][2] * inv1, Oacc[mf][nf][3] * inv1);
        }
    }
}

// ---------------------------------------------------------------------------
// Launch
// ---------------------------------------------------------------------------
extern "C" void kernel_launch(void* const* d_in, const int* in_sizes, int n_in,
                              void* d_out, int out_size)
{
    (void)in_sizes; (void)n_in; (void)out_size;
    const float* q  = (const float*)d_in[0];
    const float* k  = (const float*)d_in[1];
    const float* v  = (const float*)d_in[2];
    const float* Wq = (const float*)d_in[3];
    const float* Wk = (const float*)d_in[4];
    const float* Wv = (const float*)d_in[5];
    const float* Wo = (const float*)d_in[6];
    float* out = (float*)d_out;

    float *gQ, *gK, *gV, *gC;
    cudaGetSymbolAddress((void**)&gQ, g_Q);
    cudaGetSymbolAddress((void**)&gK, g_K);
    cudaGetSymbolAddress((void**)&gV, g_V);
    cudaGetSymbolAddress((void**)&gC, g_ctx);

    const int attn_smem = (2 * 64 * KP + 2 * 64 * VP) * (int)sizeof(float); // 71680
    static bool attr_set = false;
    if (!attr_set) {
        cudaFuncSetAttribute(attn_mma3_kernel,
                             cudaFuncAttributeMaxDynamicSharedMemorySize,
                             attn_smem);
        attr_set = true;
    }

    dim3 ggrid(DM / 128, MTOT / 128);   // (8, 64)
    gemm_tf32_kernel<2><<<ggrid, 256>>>(q, Wq, gQ);   // Q: tf32 + 1/sqrt(dk)
    gemm_tf32_kernel<1><<<ggrid, 256>>>(k, Wk, gK);   // K: tf32
    gemm_tf32_kernel<1><<<ggrid, 256>>>(v, Wv, gV);   // V: tf32

    dim3 agrid(BATCH * HH, SEQ / QTILE);   // (64, 16)
    attn_mma3_kernel<<<agrid, 128, attn_smem>>>(gQ, gK, gV, gC);

    gemm_tf32_kernel<0><<<ggrid, 256>>>(gC, Wo, out); // plain f32 out
}

// round 7
// speedup vs baseline: 4.0454x; 1.1290x over previous
#include <cuda_runtime.h>
#include <math.h>
#include <stdint.h>

// Problem constants (fixed by the reference)
#define DM    1024
#define HH    16
#define DKH   64
#define BATCH 4
#define SEQ   2048
#define MTOT  (BATCH * SEQ)   // 8192

// ---------------------------------------------------------------------------
// Scratch (no allocations allowed -> __device__ globals)
// ---------------------------------------------------------------------------
__device__ __align__(128) float g_Q[(size_t)MTOT * DM];
__device__ __align__(128) float g_K[(size_t)MTOT * DM];
__device__ __align__(128) float g_V[(size_t)MTOT * DM];
__device__ __align__(128) float g_ctx[(size_t)MTOT * DM];
// tf32-preconverted copies of inputs (preserves R5 rounding semantics)
__device__ __align__(128) float c_q[(size_t)MTOT * DM];
__device__ __align__(128) float c_k[(size_t)MTOT * DM];
__device__ __align__(128) float c_v[(size_t)MTOT * DM];
__device__ __align__(128) float c_Wq[(size_t)DM * DM];
__device__ __align__(128) float c_Wk[(size_t)DM * DM];
__device__ __align__(128) float c_Wv[(size_t)DM * DM];
__device__ __align__(128) float c_Wo[(size_t)DM * DM];

// ---------------------------------------------------------------------------
// Helpers
// ---------------------------------------------------------------------------
__device__ __forceinline__ float f2tf32(float x) {
    uint32_t r;
    asm("cvt.rna.tf32.f32 %0, %1;" : "=r"(r) : "f"(x));
    return __uint_as_float(r);
}

__device__ __forceinline__ void mma_tf32(float (&d)[4],
                                         const uint32_t (&a)[4],
                                         const uint32_t (&b)[2]) {
    asm volatile(
        "mma.sync.aligned.m16n8k8.row.col.f32.tf32.tf32.f32 "
        "{%0,%1,%2,%3}, {%4,%5,%6,%7}, {%8,%9}, {%0,%1,%2,%3};"
        : "+f"(d[0]), "+f"(d[1]), "+f"(d[2]), "+f"(d[3])
        : "r"(a[0]), "r"(a[1]), "r"(a[2]), "r"(a[3]),
          "r"(b[0]), "r"(b[1]));
}

__device__ __forceinline__ void cp16(uint32_t dst_smem, const void* src) {
    asm volatile("cp.async.cg.shared.global [%0], [%1], 16;"
                 :: "r"(dst_smem), "l"(src));
}
__device__ __forceinline__ void cp_commit() {
    asm volatile("cp.async.commit_group;");
}
template <int N>
__device__ __forceinline__ void cp_wait() {
    asm volatile("cp.async.wait_group %0;" :: "n"(N));
}

// ---------------------------------------------------------------------------
// Elementwise tf32 pre-convert (n4 float4 elements)
// ---------------------------------------------------------------------------
__global__ __launch_bounds__(256)
void conv_tf32_kernel(const float4* __restrict__ in, float4* __restrict__ out,
                      int n4)
{
    int i = blockIdx.x * blockDim.x + threadIdx.x;
    if (i < n4) {
        float4 v = in[i];
        out[i] = make_float4(f2tf32(v.x), f2tf32(v.y), f2tf32(v.z), f2tf32(v.w));
    }
}

// ---------------------------------------------------------------------------
// cp.async pipelined TF32 GEMM NT: C[M,N] = A[M,K] * B[N,K]^T
// Inputs MUST already be tf32-rounded. CTA tile 128x128, BK=64, 2 stages.
// Stage layout: per array, two 16KB column-blocks (32 floats = 128B rows)
// with the SW128 XOR swizzle -> conflict-free fill and fragment loads.
// 256 threads = 8 warps (2m x 4n), warp tile 64x32, m16n8k8 fragments.
// MODE epilogue: 0 = plain f32, 1 = tf32, 2 = tf32(0.125*x) (Q projection).
// ---------------------------------------------------------------------------
#define TBK 64
#define NST 2
#define NKB2 (DM / TBK)                  // 16
#define ARR_BYTES (128 * 128 * 2)        // 32KB: two 16KB col-blocks
#define STG_BYTES (2 * ARR_BYTES)        // A + B = 64KB
#define SMEM_G2 (NST * STG_BYTES)        // 128KB

template <int MODE>
__global__ __launch_bounds__(256)
void gemm_cp_kernel(const float* __restrict__ A,
                    const float* __restrict__ B,
                    float* __restrict__ C)
{
    extern __shared__ __align__(128) float smf[];
    const uint32_t smem_base = (uint32_t)__cvta_generic_to_shared(smf);

    const int tid = threadIdx.x;
    const int bn = blockIdx.x * 128;
    const int bm = blockIdx.y * 128;

    const int lane = tid & 31;
    const int wid  = tid >> 5;
    const int wm   = wid >> 2;          // 0..1
    const int wn   = wid & 3;           // 0..3
    const int g    = lane >> 2;         // 0..7
    const int tg   = lane & 3;          // 0..3

    float acc[4][4][4];
#pragma unroll
    for (int i = 0; i < 4; i++)
#pragma unroll
        for (int j = 0; j < 4; j++)
#pragma unroll
            for (int c = 0; c < 4; c++) acc[i][j][c] = 0.f;

    // ---- fill one stage: A/B, 128 rows x 16 units(16B) each, swizzled ----
    auto fill = [&](int slot, int kb) {
        const uint32_t ab = smem_base + slot * STG_BYTES;
        const uint32_t bb = ab + ARR_BYTES;
        const float* Ak = A + (size_t)bm * DM + kb * TBK;
        const float* Bk = B + (size_t)bn * DM + kb * TBK;
#pragma unroll
        for (int i = 0; i < 8; i++) {
            int idx = tid + i * 256;        // 0..2047
            int row = idx >> 4;             // 0..127
            int u   = idx & 15;             // 16B unit within 64-float row
            uint32_t off = (u >> 3) * 16384 + row * 128
                         + (((u & 7) ^ (row & 7)) << 4);
            cp16(ab + off, Ak + (size_t)row * DM + u * 4);
            cp16(bb + off, Bk + (size_t)row * DM + u * 4);
        }
        cp_commit();
    };

    // swizzled float index for element (row, c) of a 128x64 block, c in [0,64)
    auto sidx = [&](int row, int c) -> int {
        return (c >> 5) * 4096 + row * 32
             + ((((c & 31) >> 2) ^ (row & 7)) << 2) + (c & 3);
    };

    fill(0, 0);
    fill(1, 1);

    for (int s = 0; s < NKB2; s++) {
        const int slot = s & 1;
        if (s < NKB2 - 1) cp_wait<1>();
        else              cp_wait<0>();
        __syncthreads();

        const float* as = smf + (size_t)slot * (STG_BYTES / 4);
        const float* bs = as + ARR_BYTES / 4;

#pragma unroll
        for (int ks = 0; ks < 8; ks++) {
            uint32_t af[4][4];
            uint32_t bf[4][2];
            const int c0 = ks * 8 + tg;
#pragma unroll
            for (int mf = 0; mf < 4; mf++) {
                const int r0 = wm * 64 + mf * 16 + g;
                af[mf][0] = __float_as_uint(as[sidx(r0,     c0)]);
                af[mf][1] = __float_as_uint(as[sidx(r0 + 8, c0)]);
                af[mf][2] = __float_as_uint(as[sidx(r0,     c0 + 4)]);
                af[mf][3] = __float_as_uint(as[sidx(r0 + 8, c0 + 4)]);
            }
#pragma unroll
            for (int nf = 0; nf < 4; nf++) {
                const int r0 = wn * 32 + nf * 8 + g;
                bf[nf][0] = __float_as_uint(bs[sidx(r0, c0)]);
                bf[nf][1] = __float_as_uint(bs[sidx(r0, c0 + 4)]);
            }
#pragma unroll
            for (int mf = 0; mf < 4; mf++)
#pragma unroll
                for (int nf = 0; nf < 4; nf++)
                    mma_tf32(acc[mf][nf], af[mf], bf[nf]);
        }

        __syncthreads();
        if (s + NST < NKB2) fill(slot, s + NST);
    }

    auto ep = [&](float x) -> float {
        if (MODE == 0) return x;
        if (MODE == 1) return f2tf32(x);
        return f2tf32(x * 0.125f);
    };

#pragma unroll
    for (int mf = 0; mf < 4; mf++) {
#pragma unroll
        for (int nf = 0; nf < 4; nf++) {
            float* cp = C + (size_t)(bm + wm * 64 + mf * 16 + g) * DM
                          + bn + wn * 32 + nf * 8 + tg * 2;
            *(float2*)cp = make_float2(ep(acc[mf][nf][0]), ep(acc[mf][nf][1]));
            *(float2*)(cp + 8 * DM) = make_float2(ep(acc[mf][nf][2]), ep(acc[mf][nf][3]));
        }
    }
}

// ---------------------------------------------------------------------------
// Tensor-core flash attention v3 (R5, verified; epilogue now tf32-rounds ctx
// — previously done by the O-GEMM's stash, so end-to-end numerics unchanged).
// ---------------------------------------------------------------------------
#define KP 68
#define VP 72
#define QTILE 128
#define NKV   (SEQ / 64)   // 32 kv tiles

__global__ __launch_bounds__(128)
void attn_mma3_kernel(const float* __restrict__ Q,
                      const float* __restrict__ K,
                      const float* __restrict__ V,
                      float* __restrict__ ctx)
{
    const int bh = blockIdx.x;
    const int b  = bh / HH;
    const int h  = bh % HH;
    const int q0 = blockIdx.y * QTILE;

    extern __shared__ float sm[];
    float* Ks = sm;                         // [2][64*KP]
    float* Vs = Ks + 2 * 64 * KP;           // [2][64*VP]

    const int tid  = threadIdx.x;
    const int lane = tid & 31;
    const int warp = tid >> 5;
    const int wq   = warp * 32;
    const int g    = lane >> 2;
    const int tg   = lane & 3;
    const int idx_lo = (lane & ~3) | (tg >> 1);
    const int idx_hi = idx_lo + 2;
    const bool odd = (tg & 1);

    const float* Kbase = K + (size_t)b * SEQ * DM + h * DKH;
    const float* Vbase = V + (size_t)b * SEQ * DM + h * DKH;

    const uint32_t ks_smem = (uint32_t)__cvta_generic_to_shared(Ks);
    const uint32_t vs_smem = (uint32_t)__cvta_generic_to_shared(Vs);

    auto prefetch = [&](int t, int buf) {
#pragma unroll
        for (int i = 0; i < 8; i++) {
            int idx = tid + i * 128;
            int row = idx >> 4;
            int c4  = (idx & 15) * 4;
            const float* ks_src = Kbase + (size_t)(t * 64 + row) * DM + c4;
            const float* vs_src = Vbase + (size_t)(t * 64 + row) * DM + c4;
            cp16(ks_smem + (buf * 64 * KP + row * KP + c4) * 4, ks_src);
            cp16(vs_smem + (buf * 64 * VP + row * VP + c4) * 4, vs_src);
        }
        cp_commit();
    };

    uint32_t qa[2][8][4];
    {
        const float* Qb = Q + ((size_t)b * SEQ + q0 + wq) * DM + h * DKH;
#pragma unroll
        for (int mf = 0; mf < 2; mf++)
#pragma unroll
            for (int ks = 0; ks < 8; ks++) {
                const float* r0 = Qb + (size_t)(mf * 16 + g) * DM + ks * 8 + tg;
                const float* r1 = r0 + (size_t)8 * DM;
                qa[mf][ks][0] = __float_as_uint(r0[0]);
                qa[mf][ks][1] = __float_as_uint(r1[0]);
                qa[mf][ks][2] = __float_as_uint(r0[4]);
                qa[mf][ks][3] = __float_as_uint(r1[4]);
            }
    }

    prefetch(0, 0);

    float m_r[2][2], l_r[2][2];
    float Oacc[2][8][4];
#pragma unroll
    for (int mf = 0; mf < 2; mf++) {
        m_r[mf][0] = -INFINITY; m_r[mf][1] = -INFINITY;
        l_r[mf][0] = 0.f;       l_r[mf][1] = 0.f;
#pragma unroll
        for (int nf = 0; nf < 8; nf++)
#pragma unroll
            for (int c = 0; c < 4; c++) Oacc[mf][nf][c] = 0.f;
    }

    int buf = 0;
    for (int t = 0; t < NKV; t++) {
        if (t + 1 < NKV) prefetch(t + 1, buf ^ 1);
        else             cp_commit();
        cp_wait<1>();
        __syncthreads();

        const float* kt = Ks + buf * 64 * KP;
        const float* vt = Vs + buf * 64 * VP;

#pragma unroll
        for (int kc = 0; kc < 2; kc++) {
            float sacc[2][4][4];
#pragma unroll
            for (int mf = 0; mf < 2; mf++)
#pragma unroll
                for (int nf = 0; nf < 4; nf++)
#pragma unroll
                    for (int c = 0; c < 4; c++) sacc[mf][nf][c] = 0.f;

#pragma unroll
            for (int ks = 0; ks < 8; ks++) {
#pragma unroll
                for (int nf = 0; nf < 4; nf++) {
                    const float* p = &kt[(kc * 32 + nf * 8 + g) * KP + ks * 8 + tg];
                    uint32_t bf[2] = {__float_as_uint(p[0]), __float_as_uint(p[4])};
                    mma_tf32(sacc[0][nf], qa[0][ks], bf);
                    mma_tf32(sacc[1][nf], qa[1][ks], bf);
                }
            }

#pragma unroll
            for (int mf = 0; mf < 2; mf++) {
                float mx0 = -INFINITY, mx1 = -INFINITY;
#pragma unroll
                for (int nf = 0; nf < 4; nf++) {
                    mx0 = fmaxf(mx0, fmaxf(sacc[mf][nf][0], sacc[mf][nf][1]));
                    mx1 = fmaxf(mx1, fmaxf(sacc[mf][nf][2], sacc[mf][nf][3]));
                }
                mx0 = fmaxf(mx0, __shfl_xor_sync(0xffffffffu, mx0, 1));
                mx0 = fmaxf(mx0, __shfl_xor_sync(0xffffffffu, mx0, 2));
                mx1 = fmaxf(mx1, __shfl_xor_sync(0xffffffffu, mx1, 1));
                mx1 = fmaxf(mx1, __shfl_xor_sync(0xffffffffu, mx1, 2));

                const float mn0 = fmaxf(m_r[mf][0], mx0);
                const float mn1 = fmaxf(m_r[mf][1], mx1);
                const float al0 = __expf(m_r[mf][0] - mn0);
                const float al1 = __expf(m_r[mf][1] - mn1);

                float s0 = 0.f, s1 = 0.f;
#pragma unroll
                for (int nf = 0; nf < 4; nf++) {
                    float p0 = __expf(sacc[mf][nf][0] - mn0);
                    float p1 = __expf(sacc[mf][nf][1] - mn0);
                    float p2 = __expf(sacc[mf][nf][2] - mn1);
                    float p3 = __expf(sacc[mf][nf][3] - mn1);
                    sacc[mf][nf][0] = p0; sacc[mf][nf][1] = p1;
                    sacc[mf][nf][2] = p2; sacc[mf][nf][3] = p3;
                    s0 += p0 + p1;
                    s1 += p2 + p3;
                }
                s0 += __shfl_xor_sync(0xffffffffu, s0, 1);
                s0 += __shfl_xor_sync(0xffffffffu, s0, 2);
                s1 += __shfl_xor_sync(0xffffffffu, s1, 1);
                s1 += __shfl_xor_sync(0xffffffffu, s1, 2);

                m_r[mf][0] = mn0; m_r[mf][1] = mn1;
                l_r[mf][0] = l_r[mf][0] * al0 + s0;
                l_r[mf][1] = l_r[mf][1] * al1 + s1;

#pragma unroll
                for (int nf = 0; nf < 8; nf++) {
                    Oacc[mf][nf][0] *= al0; Oacc[mf][nf][1] *= al0;
                    Oacc[mf][nf][2] *= al1; Oacc[mf][nf][3] *= al1;
                }
            }

            uint32_t af[2][4][4];
#pragma unroll
            for (int mf = 0; mf < 2; mf++)
#pragma unroll
                for (int nf = 0; nf < 4; nf++) {
                    float v0l = __shfl_sync(0xffffffffu, sacc[mf][nf][0], idx_lo);
                    float v1l = __shfl_sync(0xffffffffu, sacc[mf][nf][1], idx_lo);
                    float v2l = __shfl_sync(0xffffffffu, sacc[mf][nf][2], idx_lo);
                    float v3l = __shfl_sync(0xffffffffu, sacc[mf][nf][3], idx_lo);
                    float v0h = __shfl_sync(0xffffffffu, sacc[mf][nf][0], idx_hi);
                    float v1h = __shfl_sync(0xffffffffu, sacc[mf][nf][1], idx_hi);
                    float v2h = __shfl_sync(0xffffffffu, sacc[mf][nf][2], idx_hi);
                    float v3h = __shfl_sync(0xffffffffu, sacc[mf][nf][3], idx_hi);
                    af[mf][nf][0] = __float_as_uint(f2tf32(odd ? v1l : v0l));
                    af[mf][nf][1] = __float_as_uint(f2tf32(odd ? v3l : v2l));
                    af[mf][nf][2] = __float_as_uint(f2tf32(odd ? v1h : v0h));
                    af[mf][nf][3] = __float_as_uint(f2tf32(odd ? v3h : v2h));
                }

#pragma unroll
            for (int ksl = 0; ksl < 4; ksl++) {
#pragma unroll
                for (int nf = 0; nf < 8; nf++) {
                    uint32_t bf[2] = {
                        __float_as_uint(vt[(kc * 32 + ksl * 8 + tg) * VP + nf * 8 + g]),
                        __float_as_uint(vt[(kc * 32 + ksl * 8 + tg + 4) * VP + nf * 8 + g])
                    };
                    mma_tf32(Oacc[0][nf], af[0][ksl], bf);
                    mma_tf32(Oacc[1][nf], af[1][ksl], bf);
                }
            }
        }

        __syncthreads();
        buf ^= 1;
    }

    // epilogue: tf32-rounded ctx (matches the rounding the O-GEMM stash did)
#pragma unroll
    for (int mf = 0; mf < 2; mf++) {
        const float inv0 = 1.f / l_r[mf][0];
        const float inv1 = 1.f / l_r[mf][1];
        float* out = ctx + ((size_t)b * SEQ + q0 + wq + mf * 16) * DM + h * DKH;
#pragma unroll
        for (int nf = 0; nf < 8; nf++) {
            *(float2*)&out[(size_t)g * DM + nf * 8 + tg * 2] =
                make_float2(f2tf32(Oacc[mf][nf][0] * inv0), f2tf32(Oacc[mf][nf][1] * inv0));
            *(float2*)&out[(size_t)(g + 8) * DM + nf * 8 + tg * 2] =
                make_float2(f2tf32(Oacc[mf][nf][2] * inv1), f2tf32(Oacc[mf][nf][3] * inv1));
        }
    }
}

// ---------------------------------------------------------------------------
// Launch
// ---------------------------------------------------------------------------
extern "C" void kernel_launch(void* const* d_in, const int* in_sizes, int n_in,
                              void* d_out, int out_size)
{
    (void)in_sizes; (void)n_in; (void)out_size;
    const float* q  = (const float*)d_in[0];
    const float* k  = (const float*)d_in[1];
    const float* v  = (const float*)d_in[2];
    const float* Wq = (const float*)d_in[3];
    const float* Wk = (const float*)d_in[4];
    const float* Wv = (const float*)d_in[5];
    const float* Wo = (const float*)d_in[6];
    float* out = (float*)d_out;

    float *gQ, *gK, *gV, *gC;
    float *cq, *ck, *cv, *cWq, *cWk, *cWv, *cWo;
    cudaGetSymbolAddress((void**)&gQ, g_Q);
    cudaGetSymbolAddress((void**)&gK, g_K);
    cudaGetSymbolAddress((void**)&gV, g_V);
    cudaGetSymbolAddress((void**)&gC, g_ctx);
    cudaGetSymbolAddress((void**)&cq, c_q);
    cudaGetSymbolAddress((void**)&ck, c_k);
    cudaGetSymbolAddress((void**)&cv, c_v);
    cudaGetSymbolAddress((void**)&cWq, c_Wq);
    cudaGetSymbolAddress((void**)&cWk, c_Wk);
    cudaGetSymbolAddress((void**)&cWv, c_Wv);
    cudaGetSymbolAddress((void**)&cWo, c_Wo);

    const int attn_smem = (2 * 64 * KP + 2 * 64 * VP) * (int)sizeof(float); // 71680
    static bool attr_set = false;
    if (!attr_set) {
        cudaFuncSetAttribute(attn_mma3_kernel,
                             cudaFuncAttributeMaxDynamicSharedMemorySize, attn_smem);
        cudaFuncSetAttribute(gemm_cp_kernel<0>,
                             cudaFuncAttributeMaxDynamicSharedMemorySize, SMEM_G2);
        cudaFuncSetAttribute(gemm_cp_kernel<1>,
                             cudaFuncAttributeMaxDynamicSharedMemorySize, SMEM_G2);
        cudaFuncSetAttribute(gemm_cp_kernel<2>,
                             cudaFuncAttributeMaxDynamicSharedMemorySize, SMEM_G2);
        attr_set = true;
    }

    // ---- pre-convert inputs to tf32 (preserves R5 rounding points) ----
    const int n4_x = MTOT * DM / 4;   // 2M float4
    const int n4_w = DM * DM / 4;     // 256K float4
    conv_tf32_kernel<<<(n4_x + 255) / 256, 256>>>((const float4*)q,  (float4*)cq,  n4_x);
    conv_tf32_kernel<<<(n4_x + 255) / 256, 256>>>((const float4*)k,  (float4*)ck,  n4_x);
    conv_tf32_kernel<<<(n4_x + 255) / 256, 256>>>((const float4*)v,  (float4*)cv,  n4_x);
    conv_tf32_kernel<<<(n4_w + 255) / 256, 256>>>((const float4*)Wq, (float4*)cWq, n4_w);
    conv_tf32_kernel<<<(n4_w + 255) / 256, 256>>>((const float4*)Wk, (float4*)cWk, n4_w);
    conv_tf32_kernel<<<(n4_w + 255) / 256, 256>>>((const float4*)Wv, (float4*)cWv, n4_w);
    conv_tf32_kernel<<<(n4_w + 255) / 256, 256>>>((const float4*)Wo, (float4*)cWo, n4_w);

    dim3 ggrid(DM / 128, MTOT / 128);   // (8, 64)
    gemm_cp_kernel<2><<<ggrid, 256, SMEM_G2>>>(cq, cWq, gQ);  // Q: tf32 + scale
    gemm_cp_kernel<1><<<ggrid, 256, SMEM_G2>>>(ck, cWk, gK);  // K: tf32
    gemm_cp_kernel<1><<<ggrid, 256, SMEM_G2>>>(cv, cWv, gV);  // V: tf32

    dim3 agrid(BATCH * HH, SEQ / QTILE);   // (64, 16)
    attn_mma3_kernel<<<agrid, 128, attn_smem>>>(gQ, gK, gV, gC);

    gemm_cp_kernel<0><<<ggrid, 256, SMEM_G2>>>(gC, cWo, out); // plain f32 out
}